// round 14
// baseline (speedup 1.0000x reference)
#include <cuda_runtime.h>
#include <cuda_bf16.h>
#include <math.h>
#include <stdint.h>

#define CEPS 1e-5f

// ---------------- scratch (device globals; allocations forbidden) ----------------
__device__ float g_qf[8 * 4096 * 256];
__device__ float g_kf[8 * 1024 * 256];
__device__ float g_query[8 * 4096 * 256];
__device__ float g_kv[8 * 1024 * 256];
__device__ float g_value[8 * 8 * 1024 * 32];
__device__ float g_awlog[8 * 4096 * 32];
__device__ float g_agg[8 * 4096 * 256];
__device__ float g_attn[8 * 4096 * 256];
__device__ float g_scale[2][256];
__device__ float g_shift[2][256];
__device__ float g_offs[64];
__device__ float g_wB[2 * 589824];           // conv weights tf32, [oc][tap*256+ic], k-pair-interleaved
__device__ float g_wT[2 * 65536 + 8192];     // vprojT(itl tf32) | oprojT(itl tf32) | awT(fp32)

// ---------------- PTX helpers ----------------------------------------------------
__device__ __forceinline__ void mma16816(float* d, const uint32_t* a, uint32_t b0,
                                         uint32_t b1) {
    asm volatile(
        "mma.sync.aligned.m16n8k16.row.col.f32.bf16.bf16.f32 "
        "{%0,%1,%2,%3}, {%4,%5,%6,%7}, {%8,%9}, {%0,%1,%2,%3};\n"
        : "+f"(d[0]), "+f"(d[1]), "+f"(d[2]), "+f"(d[3])
        : "r"(a[0]), "r"(a[1]), "r"(a[2]), "r"(a[3]), "r"(b0), "r"(b1));
}
__device__ __forceinline__ void mma1688t(float* d, const uint32_t* a, uint32_t b0,
                                         uint32_t b1) {
    asm volatile(
        "mma.sync.aligned.m16n8k8.row.col.f32.tf32.tf32.f32 "
        "{%0,%1,%2,%3}, {%4,%5,%6,%7}, {%8,%9}, {%0,%1,%2,%3};\n"
        : "+f"(d[0]), "+f"(d[1]), "+f"(d[2]), "+f"(d[3])
        : "r"(a[0]), "r"(a[1]), "r"(a[2]), "r"(a[3]), "r"(b0), "r"(b1));
}
__device__ __forceinline__ void ldmx4(uint32_t* r, uint32_t addr) {
    asm volatile("ldmatrix.sync.aligned.m8n8.x4.shared.b16 {%0,%1,%2,%3}, [%4];"
                 : "=r"(r[0]), "=r"(r[1]), "=r"(r[2]), "=r"(r[3]) : "r"(addr));
}
__device__ __forceinline__ void ldmx4t(uint32_t* r, uint32_t addr) {
    asm volatile("ldmatrix.sync.aligned.m8n8.x4.trans.shared.b16 {%0,%1,%2,%3}, [%4];"
                 : "=r"(r[0]), "=r"(r[1]), "=r"(r[2]), "=r"(r[3]) : "r"(addr));
}
__device__ __forceinline__ uint32_t smem_u32(const void* p) {
    uint32_t a;
    asm("{ .reg .u64 t; cvta.to.shared.u64 t, %1; cvt.u32.u64 %0, t; }" : "=r"(a) : "l"(p));
    return a;
}
__device__ __forceinline__ void split2(float x, float y, uint32_t& hi, uint32_t& lo) {
    __nv_bfloat162 h = __floats2bfloat162_rn(x, y);
    float2 f = __bfloat1622float2(h);
    __nv_bfloat162 l = __floats2bfloat162_rn(x - f.x, y - f.y);
    hi = *reinterpret_cast<uint32_t*>(&h);
    lo = *reinterpret_cast<uint32_t*>(&l);
}
__device__ __forceinline__ uint32_t to_tf32(float x) {
    uint32_t r;
    asm("cvt.rna.tf32.f32 %0, %1;" : "=r"(r) : "f"(x));
    return r;
}
__device__ __forceinline__ void cpasync16(uint32_t dst, const void* src) {
    asm volatile("cp.async.ca.shared.global [%0], [%1], 16;" :: "r"(dst), "l"(src));
}
#define CP_COMMIT() asm volatile("cp.async.commit_group;" ::: "memory")
#define CP_WAIT0() asm volatile("cp.async.wait_group 0;" ::: "memory")

// ---------------- prep ------------------------------------------------------------
__global__ void prep_kernel(const float* __restrict__ qcb, const float* __restrict__ qg,
                            const float* __restrict__ qbb, const float* __restrict__ qm,
                            const float* __restrict__ qv,
                            const float* __restrict__ kcb, const float* __restrict__ kg,
                            const float* __restrict__ kbb, const float* __restrict__ km,
                            const float* __restrict__ kvv,
                            const float* __restrict__ off_res) {
    int t = threadIdx.x;
    if (t < 256) {
        float a = qg[t] * rsqrtf(qv[t] + CEPS);
        g_scale[0][t] = a;
        g_shift[0][t] = (qcb[t] - qm[t]) * a + qbb[t];
        float ak = kg[t] * rsqrtf(kvv[t] + CEPS);
        g_scale[1][t] = ak;
        g_shift[1][t] = (kcb[t] - km[t]) * ak + kbb[t];
    }
    if (t < 64) {
        int h = t >> 3, p = (t >> 1) & 3, d = t & 1;
        double PI2 = 6.283185307179586476925287;
        double th = PI2 * (double)p / 4.0 + PI2 * (double)h / 8.0;
        double r = 1.0 + (double)p;
        g_offs[t] = (float)(d == 0 ? r * cos(th) : r * sin(th)) + off_res[t];
    }
}

// conv weight reorder + tf32 + k-pair interleave within each 8-k group
__global__ void convw_kernel(const float* __restrict__ w, float* __restrict__ out) {
    int i = blockIdx.x * 256 + threadIdx.x;
    if (i < 256 * 2304) {
        int oc = i / 2304, kk = i - oc * 2304;
        int jp = kk & 7;
        int j = ((jp & 1) << 2) | (jp >> 1);
        int k = (kk & ~7) | j;
        int tap = k >> 8, ic = k & 255;
        uint32_t v = to_tf32(w[(oc * 256 + ic) * 9 + tap]);
        out[i] = __uint_as_float(v);
    }
}

// projection weight: w[k][n] ([256][256] row-major) -> out[n][kk] tf32, k-pair-itl
__global__ void wtprep_kernel(const float* __restrict__ w, float* __restrict__ out) {
    int i = blockIdx.x * 256 + threadIdx.x;
    if (i < 65536) {
        int n = i >> 8, kk = i & 255;
        int jp = kk & 7;
        int j = ((jp & 1) << 2) | (jp >> 1);
        int k = (kk & ~7) | j;
        uint32_t v = to_tf32(w[k * 256 + n]);
        out[i] = __uint_as_float(v);
    }
}

__global__ void transpose_kernel(const float* __restrict__ s, float* __restrict__ d,
                                 int R, int C) {
    int i = blockIdx.x * 256 + threadIdx.x;
    if (i < R * C) {
        int r = i / C, c = i - r * C;
        d[(size_t)c * R + r] = s[i];
    }
}

// ---------------- tf32 implicit-GEMM conv3x3 + BN + ReLU (R7-proven) -------------
template <int LOGW>
__global__ __launch_bounds__(512, 1) void tconv(const float* __restrict__ A,
                                                const float* __restrict__ Bw,
                                                const float* __restrict__ e0,
                                                const float* __restrict__ e1,
                                                float* __restrict__ out) {
    constexpr int W_ = 1 << LOGW, H_ = W_;
    constexpr int PA = 544;
    constexpr int SZA = 32 * PA;            // 17408
    constexpr int PB = 160;
    constexpr int SZB = 256 * PB;           // 40960
    constexpr int OFB = 2 * SZA;
    extern __shared__ char smem[];
    const int t = threadIdx.x, wid = t >> 5, lane = t & 31;
    const int m0 = blockIdx.x * 128;
    const int wm = (wid >> 2) * 32, wn = (wid & 3) * 64;
    const int grp = lane >> 2, tid4 = lane & 3;
    const uint32_t sb = smem_u32(smem);

    float acc[2][8][4];
#pragma unroll
    for (int a = 0; a < 2; a++)
#pragma unroll
        for (int b = 0; b < 8; b++)
#pragma unroll
            for (int c = 0; c < 4; c++) acc[a][b][c] = 0.f;

    const int kl = t >> 4, g = t & 15, moff = g * 8;
    const int p0 = m0 + moff;
    const int bb = p0 >> (2 * LOGW);
    const int pix = p0 & (H_ * W_ - 1);
    const int y = pix >> LOGW, x0 = pix & (W_ - 1);
    const bool vlo = (x0 > 0), vhi = (x0 + 8 < W_);

    float wv[16];

    auto ldg = [&](int ck, int nb) {
        const int k0 = ck << 5;
        const int tap = k0 >> 8;
        const int ky = tap / 3 - 1;
        const int ic = (k0 & 255) + kl;
        const int yy = y + ky;
        const bool vy = (unsigned)yy < (unsigned)H_;
        const float* src = A + (((size_t)(bb * 256 + ic) * H_ + yy) << LOGW) + x0 - 4;
#pragma unroll
        for (int j = 0; j < 4; j++) {
            float4 v = make_float4(0.f, 0.f, 0.f, 0.f);
            bool ok = vy && (j > 0 || vlo) && (j < 3 || vhi);
            if (ok) v = __ldg((const float4*)(src + 4 * j));
            wv[4 * j] = v.x; wv[4 * j + 1] = v.y; wv[4 * j + 2] = v.z; wv[4 * j + 3] = v.w;
        }
        const int n = t >> 1, hf = t & 1;
        const float* bs = Bw + (size_t)n * 2304 + k0 + hf * 16;
        uint32_t bd = sb + OFB + nb * SZB + n * PB + hf * 64;
#pragma unroll
        for (int j = 0; j < 4; j++) cpasync16(bd + j * 16, bs + j * 4);
        CP_COMMIT();
    };

    auto stage_a = [&](int nb, int kx) {
        char* aB = smem + nb * SZA;
        uint32_t u[8];
        if (kx == -1) {
#pragma unroll
            for (int j = 0; j < 8; j++) u[j] = to_tf32(wv[3 + j]);
        } else if (kx == 0) {
#pragma unroll
            for (int j = 0; j < 8; j++) u[j] = to_tf32(wv[4 + j]);
        } else {
#pragma unroll
            for (int j = 0; j < 8; j++) u[j] = to_tf32(wv[5 + j]);
        }
        uint4* d = (uint4*)(aB + kl * PA + moff * 4);
        d[0] = make_uint4(u[0], u[1], u[2], u[3]);
        d[1] = make_uint4(u[4], u[5], u[6], u[7]);
    };

    auto compute = [&](int buf) {
        const char* aB = smem + buf * SZA;
        const char* bB = smem + OFB + buf * SZB;
#pragma unroll
        for (int ks = 0; ks < 4; ks++) {
            const int ko = ks * 8;
            uint32_t af[2][4];
#pragma unroll
            for (int mi = 0; mi < 2; mi++) {
                int r = wm + mi * 16 + grp;
                const char* a0 = aB + (ko + tid4) * PA + r * 4;
                af[mi][0] = *(const uint32_t*)(a0);
                af[mi][1] = *(const uint32_t*)(a0 + 32);
                af[mi][2] = *(const uint32_t*)(a0 + 4 * PA);
                af[mi][3] = *(const uint32_t*)(a0 + 4 * PA + 32);
            }
#pragma unroll
            for (int np = 0; np < 8; np++) {
                int n = wn + np * 8 + grp;
                uint2 bv = *(const uint2*)(bB + n * PB + ko * 4 + tid4 * 8);
                mma1688t(acc[0][np], af[0], bv.x, bv.y);
                mma1688t(acc[1][np], af[1], bv.x, bv.y);
            }
        }
    };

    const int nk = 72;
    ldg(0, 0);
    stage_a(0, -1);
    CP_WAIT0();
    __syncthreads();

    for (int i = 0; i < nk; i++) {
        const int buf = i & 1, nb = buf ^ 1;
        int kxn = 0;
        if (i + 1 < nk) {
            ldg(i + 1, nb);
            kxn = ((i + 1) >> 3) % 3 - 1;
        }
        compute(buf);
        if (i + 1 < nk) {
            stage_a(nb, kxn);
            CP_WAIT0();
        }
        __syncthreads();
    }

#pragma unroll
    for (int mi = 0; mi < 2; mi++)
#pragma unroll
        for (int np = 0; np < 8; np++) {
            int r0 = m0 + wm + mi * 16 + grp;
            int c = wn + np * 8 + tid4 * 2;
            float s0 = e0[c], s1 = e0[c + 1], h0 = e1[c], h1 = e1[c + 1];
            float v00 = fmaxf(acc[mi][np][0] * s0 + h0, 0.f);
            float v01 = fmaxf(acc[mi][np][1] * s1 + h1, 0.f);
            float v10 = fmaxf(acc[mi][np][2] * s0 + h0, 0.f);
            float v11 = fmaxf(acc[mi][np][3] * s1 + h1, 0.f);
            *(float2*)&out[(size_t)r0 * 256 + c] = make_float2(v00, v01);
            *(float2*)&out[(size_t)(r0 + 8) * 256 + c] = make_float2(v10, v11);
        }
}

// ---------------- tf32 projection GEMM (tconv skeleton): out = A[M,256] x W^T ----
// MODE 0: out[row][256] = acc + bias[c];  MODE 1: vproj scatter to [B,nH,HW,dh]
template <int MODE>
__global__ __launch_bounds__(512, 1) void tproj(const float* __restrict__ A,
                                                const float* __restrict__ Bw,
                                                const float* __restrict__ bias,
                                                float* __restrict__ out) {
    constexpr int PA = 544;
    constexpr int SZA = 32 * PA;
    constexpr int PB = 160;
    constexpr int SZB = 256 * PB;
    constexpr int OFB = 2 * SZA;
    extern __shared__ char smem[];
    const int t = threadIdx.x, wid = t >> 5, lane = t & 31;
    const int m0 = blockIdx.x * 128;
    const int wm = (wid >> 2) * 32, wn = (wid & 3) * 64;
    const int grp = lane >> 2, tid4 = lane & 3;
    const uint32_t sb = smem_u32(smem);

    float acc[2][8][4];
#pragma unroll
    for (int a = 0; a < 2; a++)
#pragma unroll
        for (int b = 0; b < 8; b++)
#pragma unroll
            for (int c = 0; c < 4; c++) acc[a][b][c] = 0.f;

    const int mrow = t & 127, kh = (t >> 7) * 8;   // 4 k-groups of 8

    auto ldgB = [&](int ck, int nb) {
        const int k0 = ck << 5;
        const int n = t >> 1, hf = t & 1;
        const float* bs = Bw + (size_t)n * 256 + k0 + hf * 16;
        uint32_t bd = sb + OFB + nb * SZB + n * PB + hf * 64;
#pragma unroll
        for (int j = 0; j < 4; j++) cpasync16(bd + j * 16, bs + j * 4);
        CP_COMMIT();
    };

    auto stage_a = [&](int ck, int nb) {
        const int k0 = ck << 5;
        const float* src = A + (size_t)(m0 + mrow) * 256 + k0 + kh;
        float4 v0 = __ldg((const float4*)src);
        float4 v1 = __ldg((const float4*)(src + 4));
        float w8[8] = {v0.x, v0.y, v0.z, v0.w, v1.x, v1.y, v1.z, v1.w};
        char* aB = smem + nb * SZA;
#pragma unroll
        for (int j = 0; j < 8; j++)
            *(uint32_t*)(aB + (kh + j) * PA + mrow * 4) = to_tf32(w8[j]);
    };

    auto compute = [&](int buf) {
        const char* aB = smem + buf * SZA;
        const char* bB = smem + OFB + buf * SZB;
#pragma unroll
        for (int ks = 0; ks < 4; ks++) {
            const int ko = ks * 8;
            uint32_t af[2][4];
#pragma unroll
            for (int mi = 0; mi < 2; mi++) {
                int r = wm + mi * 16 + grp;
                const char* a0 = aB + (ko + tid4) * PA + r * 4;
                af[mi][0] = *(const uint32_t*)(a0);
                af[mi][1] = *(const uint32_t*)(a0 + 32);
                af[mi][2] = *(const uint32_t*)(a0 + 4 * PA);
                af[mi][3] = *(const uint32_t*)(a0 + 4 * PA + 32);
            }
#pragma unroll
            for (int np = 0; np < 8; np++) {
                int n = wn + np * 8 + grp;
                uint2 bv = *(const uint2*)(bB + n * PB + ko * 4 + tid4 * 8);
                mma1688t(acc[0][np], af[0], bv.x, bv.y);
                mma1688t(acc[1][np], af[1], bv.x, bv.y);
            }
        }
    };

    const int nk = 8;
    ldgB(0, 0);
    stage_a(0, 0);
    CP_WAIT0();
    __syncthreads();

    for (int i = 0; i < nk; i++) {
        const int buf = i & 1, nb = buf ^ 1;
        if (i + 1 < nk) ldgB(i + 1, nb);
        compute(buf);
        if (i + 1 < nk) {
            stage_a(i + 1, nb);
            CP_WAIT0();
        }
        __syncthreads();
    }

#pragma unroll
    for (int mi = 0; mi < 2; mi++)
#pragma unroll
        for (int np = 0; np < 8; np++) {
            int r0 = m0 + wm + mi * 16 + grp;
            int c = wn + np * 8 + tid4 * 2;
            float b0 = bias[c], b1 = bias[c + 1];
            float v00 = acc[mi][np][0] + b0, v01 = acc[mi][np][1] + b1;
            float v10 = acc[mi][np][2] + b0, v11 = acc[mi][np][3] + b1;
            if (MODE == 1) {
                int h = c >> 5, d = c & 31;
                int r1 = r0 + 8;
                *(float2*)&out[((size_t)(((r0 >> 10) * 8 + h) * 1024 + (r0 & 1023))) * 32 + d] =
                    make_float2(v00, v01);
                *(float2*)&out[((size_t)(((r1 >> 10) * 8 + h) * 1024 + (r1 & 1023))) * 32 + d] =
                    make_float2(v10, v11);
            } else {
                *(float2*)&out[(size_t)r0 * 256 + c] = make_float2(v00, v01);
                *(float2*)&out[(size_t)(r0 + 8) * 256 + c] = make_float2(v10, v11);
            }
        }
}

// ---------------- bf16 HMMA GEMM (aw logits only) --------------------------------
template <int BM, int BN, int WGM, int WGN>
__global__ __launch_bounds__(256, 1) void tgemm(const float* __restrict__ A,
                                                const float* __restrict__ B,
                                                const float* __restrict__ e0,
                                                float* __restrict__ out, int K) {
    constexpr int WM = BM / WGM, WN = BN / WGN;
    constexpr int MI = WM / 16, NT = WN / 8, NT2 = WN / 16;
    constexpr int PA = BM * 2 + 16;
    constexpr int SZA = 32 * PA;
    constexpr int SZB = BN * 80;
    constexpr int EPTA = BM / 8;
    constexpr int EPTB = BN / 8;
    extern __shared__ char smem[];
    const uint32_t sb = smem_u32(smem);
    const int t = threadIdx.x, wid = t >> 5, lane = t & 31;
    const int m0 = blockIdx.x * BM;
    const int wm = (wid / WGN) * WM, wn = (wid % WGN) * WN;
    const int lq = lane & 7, lb3 = (lane >> 3) & 1, lb4 = (lane >> 4) & 1;

    float acc[MI][NT][4];
#pragma unroll
    for (int a = 0; a < MI; a++)
#pragma unroll
        for (int b = 0; b < NT; b++)
#pragma unroll
            for (int c = 0; c < 4; c++) acc[a][b][c] = 0.f;

    float va[EPTA], vb[EPTB];
    const int nk = K >> 5;

    auto ldg = [&](int ck) {
        const int k0 = ck << 5;
        const float4* s = (const float4*)(A + (size_t)(m0 + t) * K + k0);
#pragma unroll
        for (int j = 0; j < 8; j++) ((float4*)va)[j] = __ldg(s + j);
        const float4* s2 = (const float4*)(B + (size_t)(t >> 3) * K + k0 + (t & 7) * 4);
        ((float4*)vb)[0] = __ldg(s2);
    };

    auto sts = [&](int buf) {
        char* aHi = smem + buf * (2 * SZA);
        char* aLo = aHi + SZA;
        char* bHi = smem + 4 * SZA + buf * (2 * SZB);
        char* bLo = bHi + SZB;
#pragma unroll
        for (int j = 0; j < 32; j++) {
            __nv_bfloat16 hb = __float2bfloat16(va[j]);
            float r = va[j] - __bfloat162float(hb);
            *(__nv_bfloat16*)(aHi + j * PA + t * 2) = hb;
            *(__nv_bfloat16*)(aLo + j * PA + t * 2) = __float2bfloat16(r);
        }
        int n = t >> 3, kq = (t & 7) * 4;
        uint32_t* h = (uint32_t*)(bHi + n * 80 + kq * 2);
        uint32_t* l = (uint32_t*)(bLo + n * 80 + kq * 2);
#pragma unroll
        for (int j = 0; j < 2; j++) {
            uint32_t hh, ll;
            split2(vb[2 * j], vb[2 * j + 1], hh, ll);
            h[j] = hh;
            l[j] = ll;
        }
    };

    auto compute = [&](int buf) {
        uint32_t aHi = sb + buf * (2 * SZA), aLo = aHi + SZA;
        uint32_t bHi = sb + 4 * SZA + buf * (2 * SZB), bLo = bHi + SZB;
#pragma unroll
        for (int ks = 0; ks < 2; ks++) {
            uint32_t ah[MI][4], al[MI][4];
#pragma unroll
            for (int mi = 0; mi < MI; mi++) {
                uint32_t ao = (uint32_t)((ks * 16 + lq + lb4 * 8) * PA +
                                         (wm + mi * 16 + lb3 * 8) * 2);
                ldmx4t(ah[mi], aHi + ao);
                ldmx4t(al[mi], aLo + ao);
            }
#pragma unroll
            for (int np = 0; np < NT2; np++) {
                uint32_t bo = (uint32_t)((wn + np * 16 + lq + lb3 * 8) * 80 +
                                         (ks * 16 + lb4 * 8) * 2);
                uint32_t bh[4], bl[4];
                ldmx4(bh, bHi + bo);
                ldmx4(bl, bLo + bo);
#pragma unroll
                for (int mi = 0; mi < MI; mi++) {
                    mma16816(acc[mi][2 * np], ah[mi], bh[0], bh[2]);
                    mma16816(acc[mi][2 * np + 1], ah[mi], bh[1], bh[3]);
                    mma16816(acc[mi][2 * np], al[mi], bh[0], bh[2]);
                    mma16816(acc[mi][2 * np + 1], al[mi], bh[1], bh[3]);
                    mma16816(acc[mi][2 * np], ah[mi], bl[0], bl[2]);
                    mma16816(acc[mi][2 * np + 1], ah[mi], bl[1], bl[3]);
                }
            }
        }
    };

    ldg(0);
    sts(0);
    __syncthreads();
    for (int i = 0; i < nk; i++) {
        if (i + 1 < nk) ldg(i + 1);
        compute(i & 1);
        if (i + 1 < nk) sts((i + 1) & 1);
        __syncthreads();
    }

#pragma unroll
    for (int mi = 0; mi < MI; mi++)
#pragma unroll
        for (int nt = 0; nt < NT; nt++) {
            int r0 = m0 + wm + mi * 16 + (lane >> 2);
            int c = wn + nt * 8 + (lane & 3) * 2;
            float b0 = e0[c], b1 = e0[c + 1];
            *(float2*)&out[(size_t)r0 * BN + c] =
                make_float2(acc[mi][nt][0] + b0, acc[mi][nt][1] + b1);
            *(float2*)&out[(size_t)(r0 + 8) * BN + c] =
                make_float2(acc[mi][nt][2] + b0, acc[mi][nt][3] + b1);
        }
}

// ---------------- LayerNorm over C=256 -------------------------------------------
__global__ __launch_bounds__(256) void ln_kernel(const float* __restrict__ in,
                                                 const float* __restrict__ g,
                                                 const float* __restrict__ b,
                                                 float* __restrict__ out, int R) {
    int w = (int)((blockIdx.x * blockDim.x + threadIdx.x) >> 5);
    int lane = threadIdx.x & 31;
    if (w >= R) return;
    const float4* p = (const float4*)(in + (size_t)w * 256);
    float4 v0 = p[lane], v1 = p[lane + 32];
    float s = v0.x + v0.y + v0.z + v0.w + v1.x + v1.y + v1.z + v1.w;
    float ss = v0.x * v0.x + v0.y * v0.y + v0.z * v0.z + v0.w * v0.w +
               v1.x * v1.x + v1.y * v1.y + v1.z * v1.z + v1.w * v1.w;
#pragma unroll
    for (int o = 16; o; o >>= 1) {
        s += __shfl_xor_sync(0xffffffffu, s, o);
        ss += __shfl_xor_sync(0xffffffffu, ss, o);
    }
    float mu = s * (1.f / 256.f);
    float rs = rsqrtf(ss * (1.f / 256.f) - mu * mu + CEPS);
    const float4* gp = (const float4*)g;
    const float4* bp = (const float4*)b;
    float4 g0 = gp[lane], g1 = gp[lane + 32];
    float4 b0 = bp[lane], b1 = bp[lane + 32];
    float4 o0, o1;
    o0.x = (v0.x - mu) * rs * g0.x + b0.x;
    o0.y = (v0.y - mu) * rs * g0.y + b0.y;
    o0.z = (v0.z - mu) * rs * g0.z + b0.z;
    o0.w = (v0.w - mu) * rs * g0.w + b0.w;
    o1.x = (v1.x - mu) * rs * g1.x + b1.x;
    o1.y = (v1.y - mu) * rs * g1.y + b1.y;
    o1.z = (v1.z - mu) * rs * g1.z + b1.z;
    o1.w = (v1.w - mu) * rs * g1.w + b1.w;
    float4* op = (float4*)(out + (size_t)w * 256);
    op[lane] = o0;
    op[lane + 32] = o1;
}

// ---------------- bilinear sampling + softmax(4) + aggregation -------------------
__device__ __forceinline__ float fetch_v(const float* __restrict__ vb, int xi, int yi,
                                         int lane) {
    if ((unsigned)xi < 32u && (unsigned)yi < 32u)
        return vb[(((yi << 5) + xi) << 5) + lane];
    return 0.f;
}
__global__ __launch_bounds__(256) void sample_agg_kernel(const float* __restrict__ vflat,
                                                         const float* __restrict__ logits,
                                                         float* __restrict__ agg) {
    int wid = blockIdx.x * 8 + (threadIdx.x >> 5);
    int lane = threadIdx.x & 31;
    int q = wid & 4095, h = (wid >> 12) & 7, b = wid >> 15;

    const float* lp = logits + ((size_t)(b * 4096 + q)) * 32 + h * 4;
    float l0 = lp[0], l1 = lp[1], l2 = lp[2], l3 = lp[3];
    float m = fmaxf(fmaxf(l0, l1), fmaxf(l2, l3));
    float e0 = expf(l0 - m), e1 = expf(l1 - m), e2 = expf(l2 - m), e3 = expf(l3 - m);
    float inv = 1.f / (e0 + e1 + e2 + e3);
    float wp_[4] = {e0 * inv, e1 * inv, e2 * inv, e3 * inv};

    int qx = q & 63, qy = q >> 6;
    float bx = (qx + 0.5f) * 0.5f, by = (qy + 0.5f) * 0.5f;
    const float* vb = vflat + ((size_t)(b * 8 + h) << 10) * 32;

    float acc = 0.f;
#pragma unroll
    for (int p = 0; p < 4; p++) {
        float x = bx + g_offs[(h * 4 + p) * 2 + 0] - 0.5f;
        float y = by + g_offs[(h * 4 + p) * 2 + 1] - 0.5f;
        float xf = floorf(x), yf = floorf(y);
        int x0 = (int)xf, y0 = (int)yf;
        float fx = x - xf, fy = y - yf;
        float v00 = fetch_v(vb, x0, y0, lane);
        float v10 = fetch_v(vb, x0 + 1, y0, lane);
        float v01 = fetch_v(vb, x0, y0 + 1, lane);
        float v11 = fetch_v(vb, x0 + 1, y0 + 1, lane);
        float gg = (1.f - fx) * (1.f - fy) * v00 + fx * (1.f - fy) * v10 +
                   (1.f - fx) * fy * v01 + fx * fy * v11;
        acc = fmaf(wp_[p], gg, acc);
    }
    agg[((size_t)(b * 4096 + q)) * 256 + h * 32 + lane] = acc;
}

// ---------------- final: q*(1+attn) -> LN -> NCHW store --------------------------
__global__ __launch_bounds__(256) void final_kernel(const float* __restrict__ query,
                                                    const float* __restrict__ attn,
                                                    const float* __restrict__ gw,
                                                    const float* __restrict__ bw,
                                                    float* __restrict__ out) {
    __shared__ float tile[32][257];
    const int pix0 = blockIdx.x * 32;
    const int warp = threadIdx.x >> 5, lane = threadIdx.x & 31;
    const float4* gp = (const float4*)gw;
    const float4* bp = (const float4*)bw;
    float4 g0 = gp[lane], g1 = gp[lane + 32];
    float4 bb0 = bp[lane], bb1 = bp[lane + 32];

    for (int j = warp; j < 32; j += 8) {
        const int pix = pix0 + j;
        const float4* qp = (const float4*)(query + (size_t)pix * 256);
        const float4* ap = (const float4*)(attn + (size_t)pix * 256);
        float4 q0 = qp[lane], q1 = qp[lane + 32];
        float4 a0 = ap[lane], a1 = ap[lane + 32];
        float4 o0, o1;
        o0.x = q0.x * (1.f + a0.x);
        o0.y = q0.y * (1.f + a0.y);
        o0.z = q0.z * (1.f + a0.z);
        o0.w = q0.w * (1.f + a0.w);
        o1.x = q1.x * (1.f + a1.x);
        o1.y = q1.y * (1.f + a1.y);
        o1.z = q1.z * (1.f + a1.z);
        o1.w = q1.w * (1.f + a1.w);
        float s = o0.x + o0.y + o0.z + o0.w + o1.x + o1.y + o1.z + o1.w;
        float ss = o0.x * o0.x + o0.y * o0.y + o0.z * o0.z + o0.w * o0.w +
                   o1.x * o1.x + o1.y * o1.y + o1.z * o1.z + o1.w * o1.w;
#pragma unroll
        for (int o = 16; o; o >>= 1) {
            s += __shfl_xor_sync(0xffffffffu, s, o);
            ss += __shfl_xor_sync(0xffffffffu, ss, o);
        }
        float mu = s * (1.f / 256.f);
        float rs = rsqrtf(ss * (1.f / 256.f) - mu * mu + CEPS);
        int i0 = lane * 4;
        tile[j][i0 + 0] = (o0.x - mu) * rs * g0.x + bb0.x;
        tile[j][i0 + 1] = (o0.y - mu) * rs * g0.y + bb0.y;
        tile[j][i0 + 2] = (o0.z - mu) * rs * g0.z + bb0.z;
        tile[j][i0 + 3] = (o0.w - mu) * rs * g0.w + bb0.w;
        tile[j][128 + i0 + 0] = (o1.x - mu) * rs * g1.x + bb1.x;
        tile[j][128 + i0 + 1] = (o1.y - mu) * rs * g1.y + bb1.y;
        tile[j][128 + i0 + 2] = (o1.z - mu) * rs * g1.z + bb1.z;
        tile[j][128 + i0 + 3] = (o1.w - mu) * rs * g1.w + bb1.w;
    }
    __syncthreads();
    const int b = pix0 >> 12;
    const int q0i = pix0 & 4095;
    for (int e = threadIdx.x; e < 8192; e += 256) {
        int c = e >> 5, j = e & 31;
        out[((size_t)(b * 256 + c) << 12) + q0i + j] = tile[j][c];
    }
}

// ---------------- launch ----------------------------------------------------------
extern "C" void kernel_launch(void* const* d_in, const int* in_sizes, int n_in,
                              void* d_out, int out_size) {
    const float* query_feat = (const float*)d_in[0];
    const float* key_feat = (const float*)d_in[1];
    const float* qc_w = (const float*)d_in[2];
    const float* kc_w = (const float*)d_in[8];
    const float* off_res = (const float*)d_in[14];
    const float* lnq_g = (const float*)d_in[15];
    const float* lnq_b = (const float*)d_in[16];
    const float* lnk_g = (const float*)d_in[17];
    const float* lnk_b = (const float*)d_in[18];
    const float* lno_g = (const float*)d_in[19];
    const float* lno_b = (const float*)d_in[20];
    const float* vproj_w = (const float*)d_in[21];
    const float* vproj_b = (const float*)d_in[22];
    const float* aw_w = (const float*)d_in[23];
    const float* aw_b = (const float*)d_in[24];
    const float* oproj_w = (const float*)d_in[25];
    const float* oproj_b = (const float*)d_in[26];

    float *p_qf, *p_kf, *p_query, *p_kv, *p_value, *p_awlog, *p_agg, *p_attn;
    float *p_scale, *p_shift, *p_wB, *p_wT;
    cudaGetSymbolAddress((void**)&p_qf, g_qf);
    cudaGetSymbolAddress((void**)&p_kf, g_kf);
    cudaGetSymbolAddress((void**)&p_query, g_query);
    cudaGetSymbolAddress((void**)&p_kv, g_kv);
    cudaGetSymbolAddress((void**)&p_value, g_value);
    cudaGetSymbolAddress((void**)&p_awlog, g_awlog);
    cudaGetSymbolAddress((void**)&p_agg, g_agg);
    cudaGetSymbolAddress((void**)&p_attn, g_attn);
    cudaGetSymbolAddress((void**)&p_scale, g_scale);
    cudaGetSymbolAddress((void**)&p_shift, g_shift);
    cudaGetSymbolAddress((void**)&p_wB, g_wB);
    cudaGetSymbolAddress((void**)&p_wT, g_wT);

    const int SMC = 2 * 17408 + 2 * 40960;                       // 116736 (tconv/tproj)
    const int SMB = 4 * (32 * (256 * 2 + 16)) + 4 * (32 * 80);   // 77824 (aw tgemm)
    cudaFuncSetAttribute(tconv<6>, cudaFuncAttributeMaxDynamicSharedMemorySize, SMC);
    cudaFuncSetAttribute(tconv<5>, cudaFuncAttributeMaxDynamicSharedMemorySize, SMC);
    cudaFuncSetAttribute(tproj<0>, cudaFuncAttributeMaxDynamicSharedMemorySize, SMC);
    cudaFuncSetAttribute(tproj<1>, cudaFuncAttributeMaxDynamicSharedMemorySize, SMC);
    cudaFuncSetAttribute(tgemm<256, 32, 8, 1>,
                         cudaFuncAttributeMaxDynamicSharedMemorySize, SMB);

    // launches 1..3: setup (tconv<6> stays the 4th launch -> ncu profiles it)
    prep_kernel<<<1, 256>>>((const float*)d_in[3], (const float*)d_in[4],
                            (const float*)d_in[5], (const float*)d_in[6],
                            (const float*)d_in[7], (const float*)d_in[9],
                            (const float*)d_in[10], (const float*)d_in[11],
                            (const float*)d_in[12], (const float*)d_in[13], off_res);
    convw_kernel<<<2304, 256>>>(qc_w, p_wB);
    convw_kernel<<<2304, 256>>>(kc_w, p_wB + 589824);

    // launch 4: conv-q (profiled)
    tconv<6><<<256, 512, SMC>>>(query_feat, p_wB, p_scale, p_shift, p_qf);
    tconv<5><<<64, 512, SMC>>>(key_feat, p_wB + 589824, p_scale + 256, p_shift + 256,
                               p_kf);

    wtprep_kernel<<<256, 256>>>(vproj_w, p_wT);
    wtprep_kernel<<<256, 256>>>(oproj_w, p_wT + 65536);
    transpose_kernel<<<32, 256>>>(aw_w, p_wT + 131072, 256, 32);

    ln_kernel<<<4096, 256>>>(p_qf, lnq_g, lnq_b, p_query, 32768);
    ln_kernel<<<1024, 256>>>(p_kf, lnk_g, lnk_b, p_kv, 8192);

    tproj<1><<<64, 512, SMC>>>(p_kv, p_wT, vproj_b, p_value);
    tgemm<256, 32, 8, 1><<<128, 256, SMB>>>(p_query, p_wT + 131072, aw_b, p_awlog, 256);

    sample_agg_kernel<<<32768, 256>>>(p_value, p_awlog, p_agg);

    tproj<0><<<256, 512, SMC>>>(p_agg, p_wT + 65536, oproj_b, p_attn);

    final_kernel<<<1024, 256>>>(p_query, p_attn, lno_g, lno_b, (float*)d_out);
}

// round 15
// speedup vs baseline: 1.0647x; 1.0647x over previous
#include <cuda_runtime.h>
#include <cuda_bf16.h>
#include <math.h>
#include <stdint.h>

#define CEPS 1e-5f

// ---------------- scratch (device globals; allocations forbidden) ----------------
__device__ float g_qf[8 * 4096 * 256];
__device__ float g_kf[8 * 1024 * 256];
__device__ float g_query[8 * 4096 * 256];
__device__ float g_kv[8 * 1024 * 256];
__device__ float g_value[8 * 8 * 1024 * 32];
__device__ float g_awlog[8 * 4096 * 32];
__device__ float g_agg[8 * 4096 * 256];
__device__ float g_attn[8 * 4096 * 256];
__device__ float g_scale[2][256];
__device__ float g_shift[2][256];
__device__ float g_offs[64];
__device__ float g_wB[2 * 589824];           // conv weights tf32, [oc][tap*256+ic], k-pair-interleaved
__device__ float g_wT[2 * 65536 + 8192];     // vprojT(itl tf32) | oprojT(itl tf32) | awT(fp32)

// ---------------- PTX helpers ----------------------------------------------------
__device__ __forceinline__ void mma16816(float* d, const uint32_t* a, uint32_t b0,
                                         uint32_t b1) {
    asm volatile(
        "mma.sync.aligned.m16n8k16.row.col.f32.bf16.bf16.f32 "
        "{%0,%1,%2,%3}, {%4,%5,%6,%7}, {%8,%9}, {%0,%1,%2,%3};\n"
        : "+f"(d[0]), "+f"(d[1]), "+f"(d[2]), "+f"(d[3])
        : "r"(a[0]), "r"(a[1]), "r"(a[2]), "r"(a[3]), "r"(b0), "r"(b1));
}
__device__ __forceinline__ void mma1688t(float* d, const uint32_t* a, uint32_t b0,
                                         uint32_t b1) {
    asm volatile(
        "mma.sync.aligned.m16n8k8.row.col.f32.tf32.tf32.f32 "
        "{%0,%1,%2,%3}, {%4,%5,%6,%7}, {%8,%9}, {%0,%1,%2,%3};\n"
        : "+f"(d[0]), "+f"(d[1]), "+f"(d[2]), "+f"(d[3])
        : "r"(a[0]), "r"(a[1]), "r"(a[2]), "r"(a[3]), "r"(b0), "r"(b1));
}
__device__ __forceinline__ void ldmx4(uint32_t* r, uint32_t addr) {
    asm volatile("ldmatrix.sync.aligned.m8n8.x4.shared.b16 {%0,%1,%2,%3}, [%4];"
                 : "=r"(r[0]), "=r"(r[1]), "=r"(r[2]), "=r"(r[3]) : "r"(addr));
}
__device__ __forceinline__ void ldmx4t(uint32_t* r, uint32_t addr) {
    asm volatile("ldmatrix.sync.aligned.m8n8.x4.trans.shared.b16 {%0,%1,%2,%3}, [%4];"
                 : "=r"(r[0]), "=r"(r[1]), "=r"(r[2]), "=r"(r[3]) : "r"(addr));
}
__device__ __forceinline__ uint32_t smem_u32(const void* p) {
    uint32_t a;
    asm("{ .reg .u64 t; cvta.to.shared.u64 t, %1; cvt.u32.u64 %0, t; }" : "=r"(a) : "l"(p));
    return a;
}
__device__ __forceinline__ void split2(float x, float y, uint32_t& hi, uint32_t& lo) {
    __nv_bfloat162 h = __floats2bfloat162_rn(x, y);
    float2 f = __bfloat1622float2(h);
    __nv_bfloat162 l = __floats2bfloat162_rn(x - f.x, y - f.y);
    hi = *reinterpret_cast<uint32_t*>(&h);
    lo = *reinterpret_cast<uint32_t*>(&l);
}
__device__ __forceinline__ uint32_t to_tf32(float x) {
    uint32_t r;
    asm("cvt.rna.tf32.f32 %0, %1;" : "=r"(r) : "f"(x));
    return r;
}
__device__ __forceinline__ void cpasync16(uint32_t dst, const void* src) {
    asm volatile("cp.async.ca.shared.global [%0], [%1], 16;" :: "r"(dst), "l"(src));
}
#define CP_COMMIT() asm volatile("cp.async.commit_group;" ::: "memory")
#define CP_WAIT0() asm volatile("cp.async.wait_group 0;" ::: "memory")

// ---------------- prep ------------------------------------------------------------
__global__ void prep_kernel(const float* __restrict__ qcb, const float* __restrict__ qg,
                            const float* __restrict__ qbb, const float* __restrict__ qm,
                            const float* __restrict__ qv,
                            const float* __restrict__ kcb, const float* __restrict__ kg,
                            const float* __restrict__ kbb, const float* __restrict__ km,
                            const float* __restrict__ kvv,
                            const float* __restrict__ off_res) {
    int t = threadIdx.x;
    if (t < 256) {
        float a = qg[t] * rsqrtf(qv[t] + CEPS);
        g_scale[0][t] = a;
        g_shift[0][t] = (qcb[t] - qm[t]) * a + qbb[t];
        float ak = kg[t] * rsqrtf(kvv[t] + CEPS);
        g_scale[1][t] = ak;
        g_shift[1][t] = (kcb[t] - km[t]) * ak + kbb[t];
    }
    if (t < 64) {
        int h = t >> 3, p = (t >> 1) & 3, d = t & 1;
        double PI2 = 6.283185307179586476925287;
        double th = PI2 * (double)p / 4.0 + PI2 * (double)h / 8.0;
        double r = 1.0 + (double)p;
        g_offs[t] = (float)(d == 0 ? r * cos(th) : r * sin(th)) + off_res[t];
    }
}

// conv weight reorder + tf32 + k-pair interleave within each 8-k group
__global__ void convw_kernel(const float* __restrict__ w, float* __restrict__ out) {
    int i = blockIdx.x * 256 + threadIdx.x;
    if (i < 256 * 2304) {
        int oc = i / 2304, kk = i - oc * 2304;
        int jp = kk & 7;
        int j = ((jp & 1) << 2) | (jp >> 1);
        int k = (kk & ~7) | j;
        int tap = k >> 8, ic = k & 255;
        uint32_t v = to_tf32(w[(oc * 256 + ic) * 9 + tap]);
        out[i] = __uint_as_float(v);
    }
}

// projection weight: w[k][n] ([256][256] row-major) -> out[n][kk] tf32, k-pair-itl
__global__ void wtprep_kernel(const float* __restrict__ w, float* __restrict__ out) {
    int i = blockIdx.x * 256 + threadIdx.x;
    if (i < 65536) {
        int n = i >> 8, kk = i & 255;
        int jp = kk & 7;
        int j = ((jp & 1) << 2) | (jp >> 1);
        int k = (kk & ~7) | j;
        uint32_t v = to_tf32(w[k * 256 + n]);
        out[i] = __uint_as_float(v);
    }
}

__global__ void transpose_kernel(const float* __restrict__ s, float* __restrict__ d,
                                 int R, int C) {
    int i = blockIdx.x * 256 + threadIdx.x;
    if (i < R * C) {
        int r = i / C, c = i - r * C;
        d[(size_t)c * R + r] = s[i];
    }
}

// ---------------- tf32 implicit-GEMM conv3x3 + BN + ReLU (R7-proven) -------------
template <int LOGW>
__global__ __launch_bounds__(512, 1) void tconv(const float* __restrict__ A,
                                                const float* __restrict__ Bw,
                                                const float* __restrict__ e0,
                                                const float* __restrict__ e1,
                                                float* __restrict__ out) {
    constexpr int W_ = 1 << LOGW, H_ = W_;
    constexpr int PA = 544;
    constexpr int SZA = 32 * PA;            // 17408
    constexpr int PB = 160;
    constexpr int SZB = 256 * PB;           // 40960
    constexpr int OFB = 2 * SZA;
    extern __shared__ char smem[];
    const int t = threadIdx.x, wid = t >> 5, lane = t & 31;
    const int m0 = blockIdx.x * 128;
    const int wm = (wid >> 2) * 32, wn = (wid & 3) * 64;
    const int grp = lane >> 2, tid4 = lane & 3;
    const uint32_t sb = smem_u32(smem);

    float acc[2][8][4];
#pragma unroll
    for (int a = 0; a < 2; a++)
#pragma unroll
        for (int b = 0; b < 8; b++)
#pragma unroll
            for (int c = 0; c < 4; c++) acc[a][b][c] = 0.f;

    const int kl = t >> 4, g = t & 15, moff = g * 8;
    const int p0 = m0 + moff;
    const int bb = p0 >> (2 * LOGW);
    const int pix = p0 & (H_ * W_ - 1);
    const int y = pix >> LOGW, x0 = pix & (W_ - 1);
    const bool vlo = (x0 > 0), vhi = (x0 + 8 < W_);

    float wv[16];

    auto ldg = [&](int ck, int nb) {
        const int k0 = ck << 5;
        const int tap = k0 >> 8;
        const int ky = tap / 3 - 1;
        const int ic = (k0 & 255) + kl;
        const int yy = y + ky;
        const bool vy = (unsigned)yy < (unsigned)H_;
        const float* src = A + (((size_t)(bb * 256 + ic) * H_ + yy) << LOGW) + x0 - 4;
#pragma unroll
        for (int j = 0; j < 4; j++) {
            float4 v = make_float4(0.f, 0.f, 0.f, 0.f);
            bool ok = vy && (j > 0 || vlo) && (j < 3 || vhi);
            if (ok) v = __ldg((const float4*)(src + 4 * j));
            wv[4 * j] = v.x; wv[4 * j + 1] = v.y; wv[4 * j + 2] = v.z; wv[4 * j + 3] = v.w;
        }
        const int n = t >> 1, hf = t & 1;
        const float* bs = Bw + (size_t)n * 2304 + k0 + hf * 16;
        uint32_t bd = sb + OFB + nb * SZB + n * PB + hf * 64;
#pragma unroll
        for (int j = 0; j < 4; j++) cpasync16(bd + j * 16, bs + j * 4);
        CP_COMMIT();
    };

    auto stage_a = [&](int nb, int kx) {
        char* aB = smem + nb * SZA;
        uint32_t u[8];
        if (kx == -1) {
#pragma unroll
            for (int j = 0; j < 8; j++) u[j] = to_tf32(wv[3 + j]);
        } else if (kx == 0) {
#pragma unroll
            for (int j = 0; j < 8; j++) u[j] = to_tf32(wv[4 + j]);
        } else {
#pragma unroll
            for (int j = 0; j < 8; j++) u[j] = to_tf32(wv[5 + j]);
        }
        uint4* d = (uint4*)(aB + kl * PA + moff * 4);
        d[0] = make_uint4(u[0], u[1], u[2], u[3]);
        d[1] = make_uint4(u[4], u[5], u[6], u[7]);
    };

    auto compute = [&](int buf) {
        const char* aB = smem + buf * SZA;
        const char* bB = smem + OFB + buf * SZB;
#pragma unroll
        for (int ks = 0; ks < 4; ks++) {
            const int ko = ks * 8;
            uint32_t af[2][4];
#pragma unroll
            for (int mi = 0; mi < 2; mi++) {
                int r = wm + mi * 16 + grp;
                const char* a0 = aB + (ko + tid4) * PA + r * 4;
                af[mi][0] = *(const uint32_t*)(a0);
                af[mi][1] = *(const uint32_t*)(a0 + 32);
                af[mi][2] = *(const uint32_t*)(a0 + 4 * PA);
                af[mi][3] = *(const uint32_t*)(a0 + 4 * PA + 32);
            }
#pragma unroll
            for (int np = 0; np < 8; np++) {
                int n = wn + np * 8 + grp;
                uint2 bv = *(const uint2*)(bB + n * PB + ko * 4 + tid4 * 8);
                mma1688t(acc[0][np], af[0], bv.x, bv.y);
                mma1688t(acc[1][np], af[1], bv.x, bv.y);
            }
        }
    };

    const int nk = 72;
    ldg(0, 0);
    stage_a(0, -1);
    CP_WAIT0();
    __syncthreads();

    for (int i = 0; i < nk; i++) {
        const int buf = i & 1, nb = buf ^ 1;
        int kxn = 0;
        if (i + 1 < nk) {
            ldg(i + 1, nb);
            kxn = ((i + 1) >> 3) % 3 - 1;
        }
        compute(buf);
        if (i + 1 < nk) {
            stage_a(nb, kxn);
            CP_WAIT0();
        }
        __syncthreads();
    }

#pragma unroll
    for (int mi = 0; mi < 2; mi++)
#pragma unroll
        for (int np = 0; np < 8; np++) {
            int r0 = m0 + wm + mi * 16 + grp;
            int c = wn + np * 8 + tid4 * 2;
            float s0 = e0[c], s1 = e0[c + 1], h0 = e1[c], h1 = e1[c + 1];
            float v00 = fmaxf(acc[mi][np][0] * s0 + h0, 0.f);
            float v01 = fmaxf(acc[mi][np][1] * s1 + h1, 0.f);
            float v10 = fmaxf(acc[mi][np][2] * s0 + h0, 0.f);
            float v11 = fmaxf(acc[mi][np][3] * s1 + h1, 0.f);
            *(float2*)&out[(size_t)r0 * 256 + c] = make_float2(v00, v01);
            *(float2*)&out[(size_t)(r0 + 8) * 256 + c] = make_float2(v10, v11);
        }
}

// ---------------- tf32 projection GEMM (tconv skeleton): out = A[M,256] x W^T ----
template <int MODE>
__global__ __launch_bounds__(512, 1) void tproj(const float* __restrict__ A,
                                                const float* __restrict__ Bw,
                                                const float* __restrict__ bias,
                                                float* __restrict__ out) {
    constexpr int PA = 544;
    constexpr int SZA = 32 * PA;
    constexpr int PB = 160;
    constexpr int SZB = 256 * PB;
    constexpr int OFB = 2 * SZA;
    extern __shared__ char smem[];
    const int t = threadIdx.x, wid = t >> 5, lane = t & 31;
    const int m0 = blockIdx.x * 128;
    const int wm = (wid >> 2) * 32, wn = (wid & 3) * 64;
    const int grp = lane >> 2, tid4 = lane & 3;
    const uint32_t sb = smem_u32(smem);

    float acc[2][8][4];
#pragma unroll
    for (int a = 0; a < 2; a++)
#pragma unroll
        for (int b = 0; b < 8; b++)
#pragma unroll
            for (int c = 0; c < 4; c++) acc[a][b][c] = 0.f;

    const int mrow = t & 127, kh = (t >> 7) * 8;

    auto ldgB = [&](int ck, int nb) {
        const int k0 = ck << 5;
        const int n = t >> 1, hf = t & 1;
        const float* bs = Bw + (size_t)n * 256 + k0 + hf * 16;
        uint32_t bd = sb + OFB + nb * SZB + n * PB + hf * 64;
#pragma unroll
        for (int j = 0; j < 4; j++) cpasync16(bd + j * 16, bs + j * 4);
        CP_COMMIT();
    };

    auto stage_a = [&](int ck, int nb) {
        const int k0 = ck << 5;
        const float* src = A + (size_t)(m0 + mrow) * 256 + k0 + kh;
        float4 v0 = __ldg((const float4*)src);
        float4 v1 = __ldg((const float4*)(src + 4));
        float w8[8] = {v0.x, v0.y, v0.z, v0.w, v1.x, v1.y, v1.z, v1.w};
        char* aB = smem + nb * SZA;
#pragma unroll
        for (int j = 0; j < 8; j++)
            *(uint32_t*)(aB + (kh + j) * PA + mrow * 4) = to_tf32(w8[j]);
    };

    auto compute = [&](int buf) {
        const char* aB = smem + buf * SZA;
        const char* bB = smem + OFB + buf * SZB;
#pragma unroll
        for (int ks = 0; ks < 4; ks++) {
            const int ko = ks * 8;
            uint32_t af[2][4];
#pragma unroll
            for (int mi = 0; mi < 2; mi++) {
                int r = wm + mi * 16 + grp;
                const char* a0 = aB + (ko + tid4) * PA + r * 4;
                af[mi][0] = *(const uint32_t*)(a0);
                af[mi][1] = *(const uint32_t*)(a0 + 32);
                af[mi][2] = *(const uint32_t*)(a0 + 4 * PA);
                af[mi][3] = *(const uint32_t*)(a0 + 4 * PA + 32);
            }
#pragma unroll
            for (int np = 0; np < 8; np++) {
                int n = wn + np * 8 + grp;
                uint2 bv = *(const uint2*)(bB + n * PB + ko * 4 + tid4 * 8);
                mma1688t(acc[0][np], af[0], bv.x, bv.y);
                mma1688t(acc[1][np], af[1], bv.x, bv.y);
            }
        }
    };

    const int nk = 8;
    ldgB(0, 0);
    stage_a(0, 0);
    CP_WAIT0();
    __syncthreads();

    for (int i = 0; i < nk; i++) {
        const int buf = i & 1, nb = buf ^ 1;
        if (i + 1 < nk) ldgB(i + 1, nb);
        compute(buf);
        if (i + 1 < nk) {
            stage_a(i + 1, nb);
            CP_WAIT0();
        }
        __syncthreads();
    }

#pragma unroll
    for (int mi = 0; mi < 2; mi++)
#pragma unroll
        for (int np = 0; np < 8; np++) {
            int r0 = m0 + wm + mi * 16 + grp;
            int c = wn + np * 8 + tid4 * 2;
            float b0 = bias[c], b1 = bias[c + 1];
            float v00 = acc[mi][np][0] + b0, v01 = acc[mi][np][1] + b1;
            float v10 = acc[mi][np][2] + b0, v11 = acc[mi][np][3] + b1;
            if (MODE == 1) {
                int h = c >> 5, d = c & 31;
                int r1 = r0 + 8;
                *(float2*)&out[((size_t)(((r0 >> 10) * 8 + h) * 1024 + (r0 & 1023))) * 32 + d] =
                    make_float2(v00, v01);
                *(float2*)&out[((size_t)(((r1 >> 10) * 8 + h) * 1024 + (r1 & 1023))) * 32 + d] =
                    make_float2(v10, v11);
            } else {
                *(float2*)&out[(size_t)r0 * 256 + c] = make_float2(v00, v01);
                *(float2*)&out[(size_t)(r0 + 8) * 256 + c] = make_float2(v10, v11);
            }
        }
}

// ---------------- bf16 HMMA GEMM (aw logits only) --------------------------------
template <int BM, int BN, int WGM, int WGN>
__global__ __launch_bounds__(256, 1) void tgemm(const float* __restrict__ A,
                                                const float* __restrict__ B,
                                                const float* __restrict__ e0,
                                                float* __restrict__ out, int K) {
    constexpr int WM = BM / WGM, WN = BN / WGN;
    constexpr int MI = WM / 16, NT = WN / 8, NT2 = WN / 16;
    constexpr int PA = BM * 2 + 16;
    constexpr int SZA = 32 * PA;
    constexpr int SZB = BN * 80;
    constexpr int EPTA = BM / 8;
    constexpr int EPTB = BN / 8;
    extern __shared__ char smem[];
    const uint32_t sb = smem_u32(smem);
    const int t = threadIdx.x, wid = t >> 5, lane = t & 31;
    const int m0 = blockIdx.x * BM;
    const int wm = (wid / WGN) * WM, wn = (wid % WGN) * WN;
    const int lq = lane & 7, lb3 = (lane >> 3) & 1, lb4 = (lane >> 4) & 1;

    float acc[MI][NT][4];
#pragma unroll
    for (int a = 0; a < MI; a++)
#pragma unroll
        for (int b = 0; b < NT; b++)
#pragma unroll
            for (int c = 0; c < 4; c++) acc[a][b][c] = 0.f;

    float va[EPTA], vb[EPTB];
    const int nk = K >> 5;

    auto ldg = [&](int ck) {
        const int k0 = ck << 5;
        const float4* s = (const float4*)(A + (size_t)(m0 + t) * K + k0);
#pragma unroll
        for (int j = 0; j < 8; j++) ((float4*)va)[j] = __ldg(s + j);
        const float4* s2 = (const float4*)(B + (size_t)(t >> 3) * K + k0 + (t & 7) * 4);
        ((float4*)vb)[0] = __ldg(s2);
    };

    auto sts = [&](int buf) {
        char* aHi = smem + buf * (2 * SZA);
        char* aLo = aHi + SZA;
        char* bHi = smem + 4 * SZA + buf * (2 * SZB);
        char* bLo = bHi + SZB;
#pragma unroll
        for (int j = 0; j < 32; j++) {
            __nv_bfloat16 hb = __float2bfloat16(va[j]);
            float r = va[j] - __bfloat162float(hb);
            *(__nv_bfloat16*)(aHi + j * PA + t * 2) = hb;
            *(__nv_bfloat16*)(aLo + j * PA + t * 2) = __float2bfloat16(r);
        }
        int n = t >> 3, kq = (t & 7) * 4;
        uint32_t* h = (uint32_t*)(bHi + n * 80 + kq * 2);
        uint32_t* l = (uint32_t*)(bLo + n * 80 + kq * 2);
#pragma unroll
        for (int j = 0; j < 2; j++) {
            uint32_t hh, ll;
            split2(vb[2 * j], vb[2 * j + 1], hh, ll);
            h[j] = hh;
            l[j] = ll;
        }
    };

    auto compute = [&](int buf) {
        uint32_t aHi = sb + buf * (2 * SZA), aLo = aHi + SZA;
        uint32_t bHi = sb + 4 * SZA + buf * (2 * SZB), bLo = bHi + SZB;
#pragma unroll
        for (int ks = 0; ks < 2; ks++) {
            uint32_t ah[MI][4], al[MI][4];
#pragma unroll
            for (int mi = 0; mi < MI; mi++) {
                uint32_t ao = (uint32_t)((ks * 16 + lq + lb4 * 8) * PA +
                                         (wm + mi * 16 + lb3 * 8) * 2);
                ldmx4t(ah[mi], aHi + ao);
                ldmx4t(al[mi], aLo + ao);
            }
#pragma unroll
            for (int np = 0; np < NT2; np++) {
                uint32_t bo = (uint32_t)((wn + np * 16 + lq + lb3 * 8) * 80 +
                                         (ks * 16 + lb4 * 8) * 2);
                uint32_t bh[4], bl[4];
                ldmx4(bh, bHi + bo);
                ldmx4(bl, bLo + bo);
#pragma unroll
                for (int mi = 0; mi < MI; mi++) {
                    mma16816(acc[mi][2 * np], ah[mi], bh[0], bh[2]);
                    mma16816(acc[mi][2 * np + 1], ah[mi], bh[1], bh[3]);
                    mma16816(acc[mi][2 * np], al[mi], bh[0], bh[2]);
                    mma16816(acc[mi][2 * np + 1], al[mi], bh[1], bh[3]);
                    mma16816(acc[mi][2 * np], ah[mi], bl[0], bl[2]);
                    mma16816(acc[mi][2 * np + 1], ah[mi], bl[1], bl[3]);
                }
            }
        }
    };

    ldg(0);
    sts(0);
    __syncthreads();
    for (int i = 0; i < nk; i++) {
        if (i + 1 < nk) ldg(i + 1);
        compute(i & 1);
        if (i + 1 < nk) sts((i + 1) & 1);
        __syncthreads();
    }

#pragma unroll
    for (int mi = 0; mi < MI; mi++)
#pragma unroll
        for (int nt = 0; nt < NT; nt++) {
            int r0 = m0 + wm + mi * 16 + (lane >> 2);
            int c = wn + nt * 8 + (lane & 3) * 2;
            float b0 = e0[c], b1 = e0[c + 1];
            *(float2*)&out[(size_t)r0 * BN + c] =
                make_float2(acc[mi][nt][0] + b0, acc[mi][nt][1] + b1);
            *(float2*)&out[(size_t)(r0 + 8) * BN + c] =
                make_float2(acc[mi][nt][2] + b0, acc[mi][nt][3] + b1);
        }
}

// ---------------- LayerNorm over C=256 -------------------------------------------
__global__ __launch_bounds__(256) void ln_kernel(const float* __restrict__ in,
                                                 const float* __restrict__ g,
                                                 const float* __restrict__ b,
                                                 float* __restrict__ out, int R) {
    int w = (int)((blockIdx.x * blockDim.x + threadIdx.x) >> 5);
    int lane = threadIdx.x & 31;
    if (w >= R) return;
    const float4* p = (const float4*)(in + (size_t)w * 256);
    float4 v0 = p[lane], v1 = p[lane + 32];
    float s = v0.x + v0.y + v0.z + v0.w + v1.x + v1.y + v1.z + v1.w;
    float ss = v0.x * v0.x + v0.y * v0.y + v0.z * v0.z + v0.w * v0.w +
               v1.x * v1.x + v1.y * v1.y + v1.z * v1.z + v1.w * v1.w;
#pragma unroll
    for (int o = 16; o; o >>= 1) {
        s += __shfl_xor_sync(0xffffffffu, s, o);
        ss += __shfl_xor_sync(0xffffffffu, ss, o);
    }
    float mu = s * (1.f / 256.f);
    float rs = rsqrtf(ss * (1.f / 256.f) - mu * mu + CEPS);
    const float4* gp = (const float4*)g;
    const float4* bp = (const float4*)b;
    float4 g0 = gp[lane], g1 = gp[lane + 32];
    float4 b0 = bp[lane], b1 = bp[lane + 32];
    float4 o0, o1;
    o0.x = (v0.x - mu) * rs * g0.x + b0.x;
    o0.y = (v0.y - mu) * rs * g0.y + b0.y;
    o0.z = (v0.z - mu) * rs * g0.z + b0.z;
    o0.w = (v0.w - mu) * rs * g0.w + b0.w;
    o1.x = (v1.x - mu) * rs * g1.x + b1.x;
    o1.y = (v1.y - mu) * rs * g1.y + b1.y;
    o1.z = (v1.z - mu) * rs * g1.z + b1.z;
    o1.w = (v1.w - mu) * rs * g1.w + b1.w;
    float4* op = (float4*)(out + (size_t)w * 256);
    op[lane] = o0;
    op[lane + 32] = o1;
}

// ---------------- bilinear sampling + softmax(4) + aggregation -------------------
__device__ __forceinline__ float fetch_v(const float* __restrict__ vb, int xi, int yi,
                                         int lane) {
    if ((unsigned)xi < 32u && (unsigned)yi < 32u)
        return vb[(((yi << 5) + xi) << 5) + lane];
    return 0.f;
}
__global__ __launch_bounds__(256) void sample_agg_kernel(const float* __restrict__ vflat,
                                                         const float* __restrict__ logits,
                                                         float* __restrict__ agg) {
    int wid = blockIdx.x * 8 + (threadIdx.x >> 5);
    int lane = threadIdx.x & 31;
    int q = wid & 4095, h = (wid >> 12) & 7, b = wid >> 15;

    const float* lp = logits + ((size_t)(b * 4096 + q)) * 32 + h * 4;
    float l0 = lp[0], l1 = lp[1], l2 = lp[2], l3 = lp[3];
    float m = fmaxf(fmaxf(l0, l1), fmaxf(l2, l3));
    float e0 = expf(l0 - m), e1 = expf(l1 - m), e2 = expf(l2 - m), e3 = expf(l3 - m);
    float inv = 1.f / (e0 + e1 + e2 + e3);
    float wp_[4] = {e0 * inv, e1 * inv, e2 * inv, e3 * inv};

    int qx = q & 63, qy = q >> 6;
    float bx = (qx + 0.5f) * 0.5f, by = (qy + 0.5f) * 0.5f;
    const float* vb = vflat + ((size_t)(b * 8 + h) << 10) * 32;

    float acc = 0.f;
#pragma unroll
    for (int p = 0; p < 4; p++) {
        float x = bx + g_offs[(h * 4 + p) * 2 + 0] - 0.5f;
        float y = by + g_offs[(h * 4 + p) * 2 + 1] - 0.5f;
        float xf = floorf(x), yf = floorf(y);
        int x0 = (int)xf, y0 = (int)yf;
        float fx = x - xf, fy = y - yf;
        float v00 = fetch_v(vb, x0, y0, lane);
        float v10 = fetch_v(vb, x0 + 1, y0, lane);
        float v01 = fetch_v(vb, x0, y0 + 1, lane);
        float v11 = fetch_v(vb, x0 + 1, y0 + 1, lane);
        float gg = (1.f - fx) * (1.f - fy) * v00 + fx * (1.f - fy) * v10 +
                   (1.f - fx) * fy * v01 + fx * fy * v11;
        acc = fmaf(wp_[p], gg, acc);
    }
    agg[((size_t)(b * 4096 + q)) * 256 + h * 32 + lane] = acc;
}

// ---------------- final: q*(1+attn) -> LN -> NCHW store --------------------------
__global__ __launch_bounds__(256) void final_kernel(const float* __restrict__ query,
                                                    const float* __restrict__ attn,
                                                    const float* __restrict__ gw,
                                                    const float* __restrict__ bw,
                                                    float* __restrict__ out) {
    __shared__ float tile[32][257];
    const int pix0 = blockIdx.x * 32;
    const int warp = threadIdx.x >> 5, lane = threadIdx.x & 31;
    const float4* gp = (const float4*)gw;
    const float4* bp = (const float4*)bw;
    float4 g0 = gp[lane], g1 = gp[lane + 32];
    float4 bb0 = bp[lane], bb1 = bp[lane + 32];

    for (int j = warp; j < 32; j += 8) {
        const int pix = pix0 + j;
        const float4* qp = (const float4*)(query + (size_t)pix * 256);
        const float4* ap = (const float4*)(attn + (size_t)pix * 256);
        float4 q0 = qp[lane], q1 = qp[lane + 32];
        float4 a0 = ap[lane], a1 = ap[lane + 32];
        float4 o0, o1;
        o0.x = q0.x * (1.f + a0.x);
        o0.y = q0.y * (1.f + a0.y);
        o0.z = q0.z * (1.f + a0.z);
        o0.w = q0.w * (1.f + a0.w);
        o1.x = q1.x * (1.f + a1.x);
        o1.y = q1.y * (1.f + a1.y);
        o1.z = q1.z * (1.f + a1.z);
        o1.w = q1.w * (1.f + a1.w);
        float s = o0.x + o0.y + o0.z + o0.w + o1.x + o1.y + o1.z + o1.w;
        float ss = o0.x * o0.x + o0.y * o0.y + o0.z * o0.z + o0.w * o0.w +
                   o1.x * o1.x + o1.y * o1.y + o1.z * o1.z + o1.w * o1.w;
#pragma unroll
        for (int o = 16; o; o >>= 1) {
            s += __shfl_xor_sync(0xffffffffu, s, o);
            ss += __shfl_xor_sync(0xffffffffu, ss, o);
        }
        float mu = s * (1.f / 256.f);
        float rs = rsqrtf(ss * (1.f / 256.f) - mu * mu + CEPS);
        int i0 = lane * 4;
        tile[j][i0 + 0] = (o0.x - mu) * rs * g0.x + bb0.x;
        tile[j][i0 + 1] = (o0.y - mu) * rs * g0.y + bb0.y;
        tile[j][i0 + 2] = (o0.z - mu) * rs * g0.z + bb0.z;
        tile[j][i0 + 3] = (o0.w - mu) * rs * g0.w + bb0.w;
        tile[j][128 + i0 + 0] = (o1.x - mu) * rs * g1.x + bb1.x;
        tile[j][128 + i0 + 1] = (o1.y - mu) * rs * g1.y + bb1.y;
        tile[j][128 + i0 + 2] = (o1.z - mu) * rs * g1.z + bb1.z;
        tile[j][128 + i0 + 3] = (o1.w - mu) * rs * g1.w + bb1.w;
    }
    __syncthreads();
    const int b = pix0 >> 12;
    const int q0i = pix0 & 4095;
    for (int e = threadIdx.x; e < 8192; e += 256) {
        int c = e >> 5, j = e & 31;
        out[((size_t)(b * 256 + c) << 12) + q0i + j] = tile[j][c];
    }
}

// ---------------- launch ----------------------------------------------------------
extern "C" void kernel_launch(void* const* d_in, const int* in_sizes, int n_in,
                              void* d_out, int out_size) {
    const float* query_feat = (const float*)d_in[0];
    const float* key_feat = (const float*)d_in[1];
    const float* qc_w = (const float*)d_in[2];
    const float* kc_w = (const float*)d_in[8];
    const float* off_res = (const float*)d_in[14];
    const float* lnq_g = (const float*)d_in[15];
    const float* lnq_b = (const float*)d_in[16];
    const float* lnk_g = (const float*)d_in[17];
    const float* lnk_b = (const float*)d_in[18];
    const float* lno_g = (const float*)d_in[19];
    const float* lno_b = (const float*)d_in[20];
    const float* vproj_w = (const float*)d_in[21];
    const float* vproj_b = (const float*)d_in[22];
    const float* aw_w = (const float*)d_in[23];
    const float* aw_b = (const float*)d_in[24];
    const float* oproj_w = (const float*)d_in[25];
    const float* oproj_b = (const float*)d_in[26];

    float *p_qf, *p_kf, *p_query, *p_kv, *p_value, *p_awlog, *p_agg, *p_attn;
    float *p_scale, *p_shift, *p_wB, *p_wT;
    cudaGetSymbolAddress((void**)&p_qf, g_qf);
    cudaGetSymbolAddress((void**)&p_kf, g_kf);
    cudaGetSymbolAddress((void**)&p_query, g_query);
    cudaGetSymbolAddress((void**)&p_kv, g_kv);
    cudaGetSymbolAddress((void**)&p_value, g_value);
    cudaGetSymbolAddress((void**)&p_awlog, g_awlog);
    cudaGetSymbolAddress((void**)&p_agg, g_agg);
    cudaGetSymbolAddress((void**)&p_attn, g_attn);
    cudaGetSymbolAddress((void**)&p_scale, g_scale);
    cudaGetSymbolAddress((void**)&p_shift, g_shift);
    cudaGetSymbolAddress((void**)&p_wB, g_wB);
    cudaGetSymbolAddress((void**)&p_wT, g_wT);

    // lazily-created side stream + fork/join events (host objects, not device mem;
    // identical work is enqueued on every call -> deterministic, capture-legal)
    static cudaStream_t s2 = nullptr;
    static cudaEvent_t evFork = nullptr, evJoin = nullptr;
    if (s2 == nullptr) {
        cudaStreamCreateWithFlags(&s2, cudaStreamNonBlocking);
        cudaEventCreateWithFlags(&evFork, cudaEventDisableTiming);
        cudaEventCreateWithFlags(&evJoin, cudaEventDisableTiming);
    }

    const int SMC = 2 * 17408 + 2 * 40960;                       // 116736 (tconv/tproj)
    const int SMB = 4 * (32 * (256 * 2 + 16)) + 4 * (32 * 80);   // 77824 (aw tgemm)
    cudaFuncSetAttribute(tconv<6>, cudaFuncAttributeMaxDynamicSharedMemorySize, SMC);
    cudaFuncSetAttribute(tconv<5>, cudaFuncAttributeMaxDynamicSharedMemorySize, SMC);
    cudaFuncSetAttribute(tproj<0>, cudaFuncAttributeMaxDynamicSharedMemorySize, SMC);
    cudaFuncSetAttribute(tproj<1>, cudaFuncAttributeMaxDynamicSharedMemorySize, SMC);
    cudaFuncSetAttribute(tgemm<256, 32, 8, 1>,
                         cudaFuncAttributeMaxDynamicSharedMemorySize, SMB);

    // ---- stream 0: prep, then fork ----
    prep_kernel<<<1, 256>>>((const float*)d_in[3], (const float*)d_in[4],
                            (const float*)d_in[5], (const float*)d_in[6],
                            (const float*)d_in[7], (const float*)d_in[9],
                            (const float*)d_in[10], (const float*)d_in[11],
                            (const float*)d_in[12], (const float*)d_in[13], off_res);
    cudaEventRecord(evFork, 0);

    // ---- side stream: the whole K branch (hidden under tconv<6>) ----
    cudaStreamWaitEvent(s2, evFork, 0);
    convw_kernel<<<2304, 256, 0, s2>>>(kc_w, p_wB + 589824);
    tconv<5><<<64, 512, SMC, s2>>>(key_feat, p_wB + 589824, p_scale + 256,
                                   p_shift + 256, p_kf);
    ln_kernel<<<1024, 256, 0, s2>>>(p_kf, lnk_g, lnk_b, p_kv, 8192);
    wtprep_kernel<<<256, 256, 0, s2>>>(vproj_w, p_wT);
    wtprep_kernel<<<256, 256, 0, s2>>>(oproj_w, p_wT + 65536);
    tproj<1><<<64, 512, SMC, s2>>>(p_kv, p_wT, vproj_b, p_value);
    cudaEventRecord(evJoin, s2);

    // ---- stream 0: Q branch ----
    convw_kernel<<<2304, 256>>>(qc_w, p_wB);
    transpose_kernel<<<32, 256>>>(aw_w, p_wT + 131072, 256, 32);
    tconv<6><<<256, 512, SMC>>>(query_feat, p_wB, p_scale, p_shift, p_qf);
    ln_kernel<<<4096, 256>>>(p_qf, lnq_g, lnq_b, p_query, 32768);
    tgemm<256, 32, 8, 1><<<128, 256, SMB>>>(p_query, p_wT + 131072, aw_b, p_awlog, 256);

    // ---- join: sample needs vproj output ----
    cudaStreamWaitEvent(0, evJoin, 0);
    sample_agg_kernel<<<32768, 256>>>(p_value, p_awlog, p_agg);
    tproj<0><<<256, 512, SMC>>>(p_agg, p_wT + 65536, oproj_b, p_attn);
    final_kernel<<<1024, 256>>>(p_query, p_attn, lno_g, lno_b, (float*)d_out);
}

// round 16
// speedup vs baseline: 1.0733x; 1.0081x over previous
#include <cuda_runtime.h>
#include <cuda_bf16.h>
#include <math.h>
#include <stdint.h>

#define CEPS 1e-5f

// ---------------- scratch (device globals; allocations forbidden) ----------------
__device__ float g_qf[8 * 4096 * 256];
__device__ float g_kf[8 * 1024 * 256];
__device__ float g_query[8 * 4096 * 256];
__device__ float g_kv[8 * 1024 * 256];
__device__ float g_value[8 * 8 * 1024 * 32];
__device__ float g_awlog[8 * 4096 * 32];
__device__ float g_agg[8 * 4096 * 256];
__device__ float g_scale[2][256];
__device__ float g_shift[2][256];
__device__ float g_offs[64];
__device__ float g_wB[2 * 589824];           // conv weights tf32, [oc][tap*256+ic], k-pair-interleaved
__device__ float g_wT[2 * 65536 + 8192];     // vprojT(itl tf32) | oprojT(itl tf32) | awT(fp32)

// ---------------- PTX helpers ----------------------------------------------------
__device__ __forceinline__ void mma16816(float* d, const uint32_t* a, uint32_t b0,
                                         uint32_t b1) {
    asm volatile(
        "mma.sync.aligned.m16n8k16.row.col.f32.bf16.bf16.f32 "
        "{%0,%1,%2,%3}, {%4,%5,%6,%7}, {%8,%9}, {%0,%1,%2,%3};\n"
        : "+f"(d[0]), "+f"(d[1]), "+f"(d[2]), "+f"(d[3])
        : "r"(a[0]), "r"(a[1]), "r"(a[2]), "r"(a[3]), "r"(b0), "r"(b1));
}
__device__ __forceinline__ void mma1688t(float* d, const uint32_t* a, uint32_t b0,
                                         uint32_t b1) {
    asm volatile(
        "mma.sync.aligned.m16n8k8.row.col.f32.tf32.tf32.f32 "
        "{%0,%1,%2,%3}, {%4,%5,%6,%7}, {%8,%9}, {%0,%1,%2,%3};\n"
        : "+f"(d[0]), "+f"(d[1]), "+f"(d[2]), "+f"(d[3])
        : "r"(a[0]), "r"(a[1]), "r"(a[2]), "r"(a[3]), "r"(b0), "r"(b1));
}
__device__ __forceinline__ void ldmx4(uint32_t* r, uint32_t addr) {
    asm volatile("ldmatrix.sync.aligned.m8n8.x4.shared.b16 {%0,%1,%2,%3}, [%4];"
                 : "=r"(r[0]), "=r"(r[1]), "=r"(r[2]), "=r"(r[3]) : "r"(addr));
}
__device__ __forceinline__ void ldmx4t(uint32_t* r, uint32_t addr) {
    asm volatile("ldmatrix.sync.aligned.m8n8.x4.trans.shared.b16 {%0,%1,%2,%3}, [%4];"
                 : "=r"(r[0]), "=r"(r[1]), "=r"(r[2]), "=r"(r[3]) : "r"(addr));
}
__device__ __forceinline__ uint32_t smem_u32(const void* p) {
    uint32_t a;
    asm("{ .reg .u64 t; cvta.to.shared.u64 t, %1; cvt.u32.u64 %0, t; }" : "=r"(a) : "l"(p));
    return a;
}
__device__ __forceinline__ void split2(float x, float y, uint32_t& hi, uint32_t& lo) {
    __nv_bfloat162 h = __floats2bfloat162_rn(x, y);
    float2 f = __bfloat1622float2(h);
    __nv_bfloat162 l = __floats2bfloat162_rn(x - f.x, y - f.y);
    hi = *reinterpret_cast<uint32_t*>(&h);
    lo = *reinterpret_cast<uint32_t*>(&l);
}
__device__ __forceinline__ uint32_t to_tf32(float x) {
    uint32_t r;
    asm("cvt.rna.tf32.f32 %0, %1;" : "=r"(r) : "f"(x));
    return r;
}
__device__ __forceinline__ void cpasync16(uint32_t dst, const void* src) {
    asm volatile("cp.async.ca.shared.global [%0], [%1], 16;" :: "r"(dst), "l"(src));
}
#define CP_COMMIT() asm volatile("cp.async.commit_group;" ::: "memory")
#define CP_WAIT0() asm volatile("cp.async.wait_group 0;" ::: "memory")

// ---------------- prep ------------------------------------------------------------
__global__ void prep_kernel(const float* __restrict__ qcb, const float* __restrict__ qg,
                            const float* __restrict__ qbb, const float* __restrict__ qm,
                            const float* __restrict__ qv,
                            const float* __restrict__ kcb, const float* __restrict__ kg,
                            const float* __restrict__ kbb, const float* __restrict__ km,
                            const float* __restrict__ kvv,
                            const float* __restrict__ off_res) {
    int t = threadIdx.x;
    if (t < 256) {
        float a = qg[t] * rsqrtf(qv[t] + CEPS);
        g_scale[0][t] = a;
        g_shift[0][t] = (qcb[t] - qm[t]) * a + qbb[t];
        float ak = kg[t] * rsqrtf(kvv[t] + CEPS);
        g_scale[1][t] = ak;
        g_shift[1][t] = (kcb[t] - km[t]) * ak + kbb[t];
    }
    if (t < 64) {
        int h = t >> 3, p = (t >> 1) & 3, d = t & 1;
        double PI2 = 6.283185307179586476925287;
        double th = PI2 * (double)p / 4.0 + PI2 * (double)h / 8.0;
        double r = 1.0 + (double)p;
        g_offs[t] = (float)(d == 0 ? r * cos(th) : r * sin(th)) + off_res[t];
    }
}

// conv weight reorder + tf32 + k-pair interleave within each 8-k group
__global__ void convw_kernel(const float* __restrict__ w, float* __restrict__ out) {
    int i = blockIdx.x * 256 + threadIdx.x;
    if (i < 256 * 2304) {
        int oc = i / 2304, kk = i - oc * 2304;
        int jp = kk & 7;
        int j = ((jp & 1) << 2) | (jp >> 1);
        int k = (kk & ~7) | j;
        int tap = k >> 8, ic = k & 255;
        uint32_t v = to_tf32(w[(oc * 256 + ic) * 9 + tap]);
        out[i] = __uint_as_float(v);
    }
}

// projection weight: w[k][n] ([256][256] row-major) -> out[n][kk] tf32, k-pair-itl
__global__ void wtprep_kernel(const float* __restrict__ w, float* __restrict__ out) {
    int i = blockIdx.x * 256 + threadIdx.x;
    if (i < 65536) {
        int n = i >> 8, kk = i & 255;
        int jp = kk & 7;
        int j = ((jp & 1) << 2) | (jp >> 1);
        int k = (kk & ~7) | j;
        uint32_t v = to_tf32(w[k * 256 + n]);
        out[i] = __uint_as_float(v);
    }
}

__global__ void transpose_kernel(const float* __restrict__ s, float* __restrict__ d,
                                 int R, int C) {
    int i = blockIdx.x * 256 + threadIdx.x;
    if (i < R * C) {
        int r = i / C, c = i - r * C;
        d[(size_t)c * R + r] = s[i];
    }
}

// ---------------- tf32 implicit-GEMM conv3x3 + BN + ReLU (R7-proven) -------------
template <int LOGW>
__global__ __launch_bounds__(512, 1) void tconv(const float* __restrict__ A,
                                                const float* __restrict__ Bw,
                                                const float* __restrict__ e0,
                                                const float* __restrict__ e1,
                                                float* __restrict__ out) {
    constexpr int W_ = 1 << LOGW, H_ = W_;
    constexpr int PA = 544;
    constexpr int SZA = 32 * PA;            // 17408
    constexpr int PB = 160;
    constexpr int SZB = 256 * PB;           // 40960
    constexpr int OFB = 2 * SZA;
    extern __shared__ char smem[];
    const int t = threadIdx.x, wid = t >> 5, lane = t & 31;
    const int m0 = blockIdx.x * 128;
    const int wm = (wid >> 2) * 32, wn = (wid & 3) * 64;
    const int grp = lane >> 2, tid4 = lane & 3;
    const uint32_t sb = smem_u32(smem);

    float acc[2][8][4];
#pragma unroll
    for (int a = 0; a < 2; a++)
#pragma unroll
        for (int b = 0; b < 8; b++)
#pragma unroll
            for (int c = 0; c < 4; c++) acc[a][b][c] = 0.f;

    const int kl = t >> 4, g = t & 15, moff = g * 8;
    const int p0 = m0 + moff;
    const int bb = p0 >> (2 * LOGW);
    const int pix = p0 & (H_ * W_ - 1);
    const int y = pix >> LOGW, x0 = pix & (W_ - 1);
    const bool vlo = (x0 > 0), vhi = (x0 + 8 < W_);

    float wv[16];

    auto ldg = [&](int ck, int nb) {
        const int k0 = ck << 5;
        const int tap = k0 >> 8;
        const int ky = tap / 3 - 1;
        const int ic = (k0 & 255) + kl;
        const int yy = y + ky;
        const bool vy = (unsigned)yy < (unsigned)H_;
        const float* src = A + (((size_t)(bb * 256 + ic) * H_ + yy) << LOGW) + x0 - 4;
#pragma unroll
        for (int j = 0; j < 4; j++) {
            float4 v = make_float4(0.f, 0.f, 0.f, 0.f);
            bool ok = vy && (j > 0 || vlo) && (j < 3 || vhi);
            if (ok) v = __ldg((const float4*)(src + 4 * j));
            wv[4 * j] = v.x; wv[4 * j + 1] = v.y; wv[4 * j + 2] = v.z; wv[4 * j + 3] = v.w;
        }
        const int n = t >> 1, hf = t & 1;
        const float* bs = Bw + (size_t)n * 2304 + k0 + hf * 16;
        uint32_t bd = sb + OFB + nb * SZB + n * PB + hf * 64;
#pragma unroll
        for (int j = 0; j < 4; j++) cpasync16(bd + j * 16, bs + j * 4);
        CP_COMMIT();
    };

    auto stage_a = [&](int nb, int kx) {
        char* aB = smem + nb * SZA;
        uint32_t u[8];
        if (kx == -1) {
#pragma unroll
            for (int j = 0; j < 8; j++) u[j] = to_tf32(wv[3 + j]);
        } else if (kx == 0) {
#pragma unroll
            for (int j = 0; j < 8; j++) u[j] = to_tf32(wv[4 + j]);
        } else {
#pragma unroll
            for (int j = 0; j < 8; j++) u[j] = to_tf32(wv[5 + j]);
        }
        uint4* d = (uint4*)(aB + kl * PA + moff * 4);
        d[0] = make_uint4(u[0], u[1], u[2], u[3]);
        d[1] = make_uint4(u[4], u[5], u[6], u[7]);
    };

    auto compute = [&](int buf) {
        const char* aB = smem + buf * SZA;
        const char* bB = smem + OFB + buf * SZB;
#pragma unroll
        for (int ks = 0; ks < 4; ks++) {
            const int ko = ks * 8;
            uint32_t af[2][4];
#pragma unroll
            for (int mi = 0; mi < 2; mi++) {
                int r = wm + mi * 16 + grp;
                const char* a0 = aB + (ko + tid4) * PA + r * 4;
                af[mi][0] = *(const uint32_t*)(a0);
                af[mi][1] = *(const uint32_t*)(a0 + 32);
                af[mi][2] = *(const uint32_t*)(a0 + 4 * PA);
                af[mi][3] = *(const uint32_t*)(a0 + 4 * PA + 32);
            }
#pragma unroll
            for (int np = 0; np < 8; np++) {
                int n = wn + np * 8 + grp;
                uint2 bv = *(const uint2*)(bB + n * PB + ko * 4 + tid4 * 8);
                mma1688t(acc[0][np], af[0], bv.x, bv.y);
                mma1688t(acc[1][np], af[1], bv.x, bv.y);
            }
        }
    };

    const int nk = 72;
    ldg(0, 0);
    stage_a(0, -1);
    CP_WAIT0();
    __syncthreads();

    for (int i = 0; i < nk; i++) {
        const int buf = i & 1, nb = buf ^ 1;
        int kxn = 0;
        if (i + 1 < nk) {
            ldg(i + 1, nb);
            kxn = ((i + 1) >> 3) % 3 - 1;
        }
        compute(buf);
        if (i + 1 < nk) {
            stage_a(nb, kxn);
            CP_WAIT0();
        }
        __syncthreads();
    }

#pragma unroll
    for (int mi = 0; mi < 2; mi++)
#pragma unroll
        for (int np = 0; np < 8; np++) {
            int r0 = m0 + wm + mi * 16 + grp;
            int c = wn + np * 8 + tid4 * 2;
            float s0 = e0[c], s1 = e0[c + 1], h0 = e1[c], h1 = e1[c + 1];
            float v00 = fmaxf(acc[mi][np][0] * s0 + h0, 0.f);
            float v01 = fmaxf(acc[mi][np][1] * s1 + h1, 0.f);
            float v10 = fmaxf(acc[mi][np][2] * s0 + h0, 0.f);
            float v11 = fmaxf(acc[mi][np][3] * s1 + h1, 0.f);
            *(float2*)&out[(size_t)r0 * 256 + c] = make_float2(v00, v01);
            *(float2*)&out[(size_t)(r0 + 8) * 256 + c] = make_float2(v10, v11);
        }
}

// ---------------- tf32 projection GEMM core (shared by tproj / tprojF) -----------
struct ProjCtx {
    float acc[2][8][4];
};

template <int MODE>
__global__ __launch_bounds__(512, 1) void tproj(const float* __restrict__ A,
                                                const float* __restrict__ Bw,
                                                const float* __restrict__ bias,
                                                float* __restrict__ out) {
    constexpr int PA = 544;
    constexpr int SZA = 32 * PA;
    constexpr int PB = 160;
    constexpr int SZB = 256 * PB;
    constexpr int OFB = 2 * SZA;
    extern __shared__ char smem[];
    const int t = threadIdx.x, wid = t >> 5, lane = t & 31;
    const int m0 = blockIdx.x * 128;
    const int wm = (wid >> 2) * 32, wn = (wid & 3) * 64;
    const int grp = lane >> 2, tid4 = lane & 3;
    const uint32_t sb = smem_u32(smem);

    float acc[2][8][4];
#pragma unroll
    for (int a = 0; a < 2; a++)
#pragma unroll
        for (int b = 0; b < 8; b++)
#pragma unroll
            for (int c = 0; c < 4; c++) acc[a][b][c] = 0.f;

    const int mrow = t & 127, kh = (t >> 7) * 8;

    auto ldgB = [&](int ck, int nb) {
        const int k0 = ck << 5;
        const int n = t >> 1, hf = t & 1;
        const float* bs = Bw + (size_t)n * 256 + k0 + hf * 16;
        uint32_t bd = sb + OFB + nb * SZB + n * PB + hf * 64;
#pragma unroll
        for (int j = 0; j < 4; j++) cpasync16(bd + j * 16, bs + j * 4);
        CP_COMMIT();
    };

    auto stage_a = [&](int ck, int nb) {
        const int k0 = ck << 5;
        const float* src = A + (size_t)(m0 + mrow) * 256 + k0 + kh;
        float4 v0 = __ldg((const float4*)src);
        float4 v1 = __ldg((const float4*)(src + 4));
        float w8[8] = {v0.x, v0.y, v0.z, v0.w, v1.x, v1.y, v1.z, v1.w};
        char* aB = smem + nb * SZA;
#pragma unroll
        for (int j = 0; j < 8; j++)
            *(uint32_t*)(aB + (kh + j) * PA + mrow * 4) = to_tf32(w8[j]);
    };

    auto compute = [&](int buf) {
        const char* aB = smem + buf * SZA;
        const char* bB = smem + OFB + buf * SZB;
#pragma unroll
        for (int ks = 0; ks < 4; ks++) {
            const int ko = ks * 8;
            uint32_t af[2][4];
#pragma unroll
            for (int mi = 0; mi < 2; mi++) {
                int r = wm + mi * 16 + grp;
                const char* a0 = aB + (ko + tid4) * PA + r * 4;
                af[mi][0] = *(const uint32_t*)(a0);
                af[mi][1] = *(const uint32_t*)(a0 + 32);
                af[mi][2] = *(const uint32_t*)(a0 + 4 * PA);
                af[mi][3] = *(const uint32_t*)(a0 + 4 * PA + 32);
            }
#pragma unroll
            for (int np = 0; np < 8; np++) {
                int n = wn + np * 8 + grp;
                uint2 bv = *(const uint2*)(bB + n * PB + ko * 4 + tid4 * 8);
                mma1688t(acc[0][np], af[0], bv.x, bv.y);
                mma1688t(acc[1][np], af[1], bv.x, bv.y);
            }
        }
    };

    const int nk = 8;
    ldgB(0, 0);
    stage_a(0, 0);
    CP_WAIT0();
    __syncthreads();

    for (int i = 0; i < nk; i++) {
        const int buf = i & 1, nb = buf ^ 1;
        if (i + 1 < nk) ldgB(i + 1, nb);
        compute(buf);
        if (i + 1 < nk) {
            stage_a(i + 1, nb);
            CP_WAIT0();
        }
        __syncthreads();
    }

#pragma unroll
    for (int mi = 0; mi < 2; mi++)
#pragma unroll
        for (int np = 0; np < 8; np++) {
            int r0 = m0 + wm + mi * 16 + grp;
            int c = wn + np * 8 + tid4 * 2;
            float b0 = bias[c], b1 = bias[c + 1];
            float v00 = acc[mi][np][0] + b0, v01 = acc[mi][np][1] + b1;
            float v10 = acc[mi][np][2] + b0, v11 = acc[mi][np][3] + b1;
            if (MODE == 1) {
                int h = c >> 5, d = c & 31;
                int r1 = r0 + 8;
                *(float2*)&out[((size_t)(((r0 >> 10) * 8 + h) * 1024 + (r0 & 1023))) * 32 + d] =
                    make_float2(v00, v01);
                *(float2*)&out[((size_t)(((r1 >> 10) * 8 + h) * 1024 + (r1 & 1023))) * 32 + d] =
                    make_float2(v10, v11);
            } else {
                *(float2*)&out[(size_t)r0 * 256 + c] = make_float2(v00, v01);
                *(float2*)&out[(size_t)(r0 + 8) * 256 + c] = make_float2(v10, v11);
            }
        }
}

// ---------------- fused oproj + q*(1+attn) + LayerNorm + NCHW store --------------
__global__ __launch_bounds__(512, 1) void tprojF(const float* __restrict__ A,
                                                 const float* __restrict__ Bw,
                                                 const float* __restrict__ bias,
                                                 const float* __restrict__ query,
                                                 const float* __restrict__ lng,
                                                 const float* __restrict__ lnb,
                                                 float* __restrict__ out) {
    constexpr int PA = 544;
    constexpr int SZA = 32 * PA;
    constexpr int PB = 160;
    constexpr int SZB = 256 * PB;
    constexpr int OFB = 2 * SZA;
    extern __shared__ char smem[];
    const int t = threadIdx.x, wid = t >> 5, lane = t & 31;
    const int m0 = blockIdx.x * 128;
    const int wm = (wid >> 2) * 32, wn = (wid & 3) * 64;
    const int grp = lane >> 2, tid4 = lane & 3;
    const uint32_t sb = smem_u32(smem);

    float acc[2][8][4];
#pragma unroll
    for (int a = 0; a < 2; a++)
#pragma unroll
        for (int b = 0; b < 8; b++)
#pragma unroll
            for (int c = 0; c < 4; c++) acc[a][b][c] = 0.f;

    const int mrow = t & 127, kh = (t >> 7) * 8;

    auto ldgB = [&](int ck, int nb) {
        const int k0 = ck << 5;
        const int n = t >> 1, hf = t & 1;
        const float* bs = Bw + (size_t)n * 256 + k0 + hf * 16;
        uint32_t bd = sb + OFB + nb * SZB + n * PB + hf * 64;
#pragma unroll
        for (int j = 0; j < 4; j++) cpasync16(bd + j * 16, bs + j * 4);
        CP_COMMIT();
    };

    auto stage_a = [&](int ck, int nb) {
        const int k0 = ck << 5;
        const float* src = A + (size_t)(m0 + mrow) * 256 + k0 + kh;
        float4 v0 = __ldg((const float4*)src);
        float4 v1 = __ldg((const float4*)(src + 4));
        float w8[8] = {v0.x, v0.y, v0.z, v0.w, v1.x, v1.y, v1.z, v1.w};
        char* aB = smem + nb * SZA;
#pragma unroll
        for (int j = 0; j < 8; j++)
            *(uint32_t*)(aB + (kh + j) * PA + mrow * 4) = to_tf32(w8[j]);
    };

    auto compute = [&](int buf) {
        const char* aB = smem + buf * SZA;
        const char* bB = smem + OFB + buf * SZB;
#pragma unroll
        for (int ks = 0; ks < 4; ks++) {
            const int ko = ks * 8;
            uint32_t af[2][4];
#pragma unroll
            for (int mi = 0; mi < 2; mi++) {
                int r = wm + mi * 16 + grp;
                const char* a0 = aB + (ko + tid4) * PA + r * 4;
                af[mi][0] = *(const uint32_t*)(a0);
                af[mi][1] = *(const uint32_t*)(a0 + 32);
                af[mi][2] = *(const uint32_t*)(a0 + 4 * PA);
                af[mi][3] = *(const uint32_t*)(a0 + 4 * PA + 32);
            }
#pragma unroll
            for (int np = 0; np < 8; np++) {
                int n = wn + np * 8 + grp;
                uint2 bv = *(const uint2*)(bB + n * PB + ko * 4 + tid4 * 8);
                mma1688t(acc[0][np], af[0], bv.x, bv.y);
                mma1688t(acc[1][np], af[1], bv.x, bv.y);
            }
        }
    };

    const int nk = 8;
    ldgB(0, 0);
    stage_a(0, 0);
    CP_WAIT0();
    __syncthreads();

    for (int i = 0; i < nk; i++) {
        const int buf = i & 1, nb = buf ^ 1;
        if (i + 1 < nk) ldgB(i + 1, nb);
        compute(buf);
        if (i + 1 < nk) {
            stage_a(i + 1, nb);
            CP_WAIT0();
        }
        __syncthreads();
    }

    // ---- fused epilogue: o = q*(1+acc+bias); LN over C=256; NCHW store ----
    float* redS = (float*)smem;  // [128 rows][4 wn-warps][2] = 1024 floats
    float s_[2][2], ss_[2][2];
#pragma unroll
    for (int mi = 0; mi < 2; mi++)
#pragma unroll
        for (int rl = 0; rl < 2; rl++) { s_[mi][rl] = 0.f; ss_[mi][rl] = 0.f; }

#pragma unroll
    for (int mi = 0; mi < 2; mi++) {
        int r0 = m0 + wm + mi * 16 + grp;
#pragma unroll
        for (int np = 0; np < 8; np++) {
            int c = wn + np * 8 + tid4 * 2;
            float b0 = bias[c], b1 = bias[c + 1];
            float2 qa = *(const float2*)&query[(size_t)r0 * 256 + c];
            float2 qb = *(const float2*)&query[(size_t)(r0 + 8) * 256 + c];
            float o00 = qa.x * (1.f + acc[mi][np][0] + b0);
            float o01 = qa.y * (1.f + acc[mi][np][1] + b1);
            float o10 = qb.x * (1.f + acc[mi][np][2] + b0);
            float o11 = qb.y * (1.f + acc[mi][np][3] + b1);
            acc[mi][np][0] = o00; acc[mi][np][1] = o01;
            acc[mi][np][2] = o10; acc[mi][np][3] = o11;
            s_[mi][0] += o00 + o01; ss_[mi][0] += o00 * o00 + o01 * o01;
            s_[mi][1] += o10 + o11; ss_[mi][1] += o10 * o10 + o11 * o11;
        }
    }
    // reduce over tid4 (lanes grp*4+tid4): xor 1, 2
#pragma unroll
    for (int mi = 0; mi < 2; mi++)
#pragma unroll
        for (int rl = 0; rl < 2; rl++) {
            float s = s_[mi][rl], ss = ss_[mi][rl];
            s += __shfl_xor_sync(0xffffffffu, s, 1);
            ss += __shfl_xor_sync(0xffffffffu, ss, 1);
            s += __shfl_xor_sync(0xffffffffu, s, 2);
            ss += __shfl_xor_sync(0xffffffffu, ss, 2);
            s_[mi][rl] = s; ss_[mi][rl] = ss;
        }
    __syncthreads();  // smem reuse: mainloop done everywhere
    if (tid4 == 0) {
#pragma unroll
        for (int mi = 0; mi < 2; mi++)
#pragma unroll
            for (int rl = 0; rl < 2; rl++) {
                int rloc = wm + mi * 16 + rl * 8 + grp;
                redS[rloc * 8 + (wid & 3) * 2 + 0] = s_[mi][rl];
                redS[rloc * 8 + (wid & 3) * 2 + 1] = ss_[mi][rl];
            }
    }
    __syncthreads();

    const int bB_ = m0 >> 12;
    const int pixBase = m0 & 4095;
#pragma unroll
    for (int mi = 0; mi < 2; mi++) {
#pragma unroll
        for (int rl = 0; rl < 2; rl++) {
            int rloc = wm + mi * 16 + rl * 8 + grp;
            float s = redS[rloc * 8 + 0] + redS[rloc * 8 + 2] + redS[rloc * 8 + 4] +
                      redS[rloc * 8 + 6];
            float ss = redS[rloc * 8 + 1] + redS[rloc * 8 + 3] + redS[rloc * 8 + 5] +
                       redS[rloc * 8 + 7];
            float mu = s * (1.f / 256.f);
            float rs = rsqrtf(ss * (1.f / 256.f) - mu * mu + CEPS);
            int pix = pixBase + rloc;
#pragma unroll
            for (int np = 0; np < 8; np++) {
                int c = wn + np * 8 + tid4 * 2;
                float o0 = acc[mi][np][2 * rl + 0];
                float o1 = acc[mi][np][2 * rl + 1];
                float r0 = (o0 - mu) * rs * __ldg(&lng[c]) + __ldg(&lnb[c]);
                float r1 = (o1 - mu) * rs * __ldg(&lng[c + 1]) + __ldg(&lnb[c + 1]);
                out[((size_t)(bB_ * 256 + c) << 12) + pix] = r0;
                out[((size_t)(bB_ * 256 + c + 1) << 12) + pix] = r1;
            }
        }
    }
}

// ---------------- bf16 HMMA GEMM (aw logits only) --------------------------------
template <int BM, int BN, int WGM, int WGN>
__global__ __launch_bounds__(256, 1) void tgemm(const float* __restrict__ A,
                                                const float* __restrict__ B,
                                                const float* __restrict__ e0,
                                                float* __restrict__ out, int K) {
    constexpr int WM = BM / WGM, WN = BN / WGN;
    constexpr int MI = WM / 16, NT = WN / 8, NT2 = WN / 16;
    constexpr int PA = BM * 2 + 16;
    constexpr int SZA = 32 * PA;
    constexpr int SZB = BN * 80;
    constexpr int EPTA = BM / 8;
    constexpr int EPTB = BN / 8;
    extern __shared__ char smem[];
    const uint32_t sb = smem_u32(smem);
    const int t = threadIdx.x, wid = t >> 5, lane = t & 31;
    const int m0 = blockIdx.x * BM;
    const int wm = (wid / WGN) * WM, wn = (wid % WGN) * WN;
    const int lq = lane & 7, lb3 = (lane >> 3) & 1, lb4 = (lane >> 4) & 1;

    float acc[MI][NT][4];
#pragma unroll
    for (int a = 0; a < MI; a++)
#pragma unroll
        for (int b = 0; b < NT; b++)
#pragma unroll
            for (int c = 0; c < 4; c++) acc[a][b][c] = 0.f;

    float va[EPTA], vb[EPTB];
    const int nk = K >> 5;

    auto ldg = [&](int ck) {
        const int k0 = ck << 5;
        const float4* s = (const float4*)(A + (size_t)(m0 + t) * K + k0);
#pragma unroll
        for (int j = 0; j < 8; j++) ((float4*)va)[j] = __ldg(s + j);
        const float4* s2 = (const float4*)(B + (size_t)(t >> 3) * K + k0 + (t & 7) * 4);
        ((float4*)vb)[0] = __ldg(s2);
    };

    auto sts = [&](int buf) {
        char* aHi = smem + buf * (2 * SZA);
        char* aLo = aHi + SZA;
        char* bHi = smem + 4 * SZA + buf * (2 * SZB);
        char* bLo = bHi + SZB;
#pragma unroll
        for (int j = 0; j < 32; j++) {
            __nv_bfloat16 hb = __float2bfloat16(va[j]);
            float r = va[j] - __bfloat162float(hb);
            *(__nv_bfloat16*)(aHi + j * PA + t * 2) = hb;
            *(__nv_bfloat16*)(aLo + j * PA + t * 2) = __float2bfloat16(r);
        }
        int n = t >> 3, kq = (t & 7) * 4;
        uint32_t* h = (uint32_t*)(bHi + n * 80 + kq * 2);
        uint32_t* l = (uint32_t*)(bLo + n * 80 + kq * 2);
#pragma unroll
        for (int j = 0; j < 2; j++) {
            uint32_t hh, ll;
            split2(vb[2 * j], vb[2 * j + 1], hh, ll);
            h[j] = hh;
            l[j] = ll;
        }
    };

    auto compute = [&](int buf) {
        uint32_t aHi = sb + buf * (2 * SZA), aLo = aHi + SZA;
        uint32_t bHi = sb + 4 * SZA + buf * (2 * SZB), bLo = bHi + SZB;
#pragma unroll
        for (int ks = 0; ks < 2; ks++) {
            uint32_t ah[MI][4], al[MI][4];
#pragma unroll
            for (int mi = 0; mi < MI; mi++) {
                uint32_t ao = (uint32_t)((ks * 16 + lq + lb4 * 8) * PA +
                                         (wm + mi * 16 + lb3 * 8) * 2);
                ldmx4t(ah[mi], aHi + ao);
                ldmx4t(al[mi], aLo + ao);
            }
#pragma unroll
            for (int np = 0; np < NT2; np++) {
                uint32_t bo = (uint32_t)((wn + np * 16 + lq + lb3 * 8) * 80 +
                                         (ks * 16 + lb4 * 8) * 2);
                uint32_t bh[4], bl[4];
                ldmx4(bh, bHi + bo);
                ldmx4(bl, bLo + bo);
#pragma unroll
                for (int mi = 0; mi < MI; mi++) {
                    mma16816(acc[mi][2 * np], ah[mi], bh[0], bh[2]);
                    mma16816(acc[mi][2 * np + 1], ah[mi], bh[1], bh[3]);
                    mma16816(acc[mi][2 * np], al[mi], bh[0], bh[2]);
                    mma16816(acc[mi][2 * np + 1], al[mi], bh[1], bh[3]);
                    mma16816(acc[mi][2 * np], ah[mi], bl[0], bl[2]);
                    mma16816(acc[mi][2 * np + 1], ah[mi], bl[1], bl[3]);
                }
            }
        }
    };

    ldg(0);
    sts(0);
    __syncthreads();
    for (int i = 0; i < nk; i++) {
        if (i + 1 < nk) ldg(i + 1);
        compute(i & 1);
        if (i + 1 < nk) sts((i + 1) & 1);
        __syncthreads();
    }

#pragma unroll
    for (int mi = 0; mi < MI; mi++)
#pragma unroll
        for (int nt = 0; nt < NT; nt++) {
            int r0 = m0 + wm + mi * 16 + (lane >> 2);
            int c = wn + nt * 8 + (lane & 3) * 2;
            float b0 = e0[c], b1 = e0[c + 1];
            *(float2*)&out[(size_t)r0 * BN + c] =
                make_float2(acc[mi][nt][0] + b0, acc[mi][nt][1] + b1);
            *(float2*)&out[(size_t)(r0 + 8) * BN + c] =
                make_float2(acc[mi][nt][2] + b0, acc[mi][nt][3] + b1);
        }
}

// ---------------- LayerNorm over C=256 -------------------------------------------
__global__ __launch_bounds__(256) void ln_kernel(const float* __restrict__ in,
                                                 const float* __restrict__ g,
                                                 const float* __restrict__ b,
                                                 float* __restrict__ out, int R) {
    int w = (int)((blockIdx.x * blockDim.x + threadIdx.x) >> 5);
    int lane = threadIdx.x & 31;
    if (w >= R) return;
    const float4* p = (const float4*)(in + (size_t)w * 256);
    float4 v0 = p[lane], v1 = p[lane + 32];
    float s = v0.x + v0.y + v0.z + v0.w + v1.x + v1.y + v1.z + v1.w;
    float ss = v0.x * v0.x + v0.y * v0.y + v0.z * v0.z + v0.w * v0.w +
               v1.x * v1.x + v1.y * v1.y + v1.z * v1.z + v1.w * v1.w;
#pragma unroll
    for (int o = 16; o; o >>= 1) {
        s += __shfl_xor_sync(0xffffffffu, s, o);
        ss += __shfl_xor_sync(0xffffffffu, ss, o);
    }
    float mu = s * (1.f / 256.f);
    float rs = rsqrtf(ss * (1.f / 256.f) - mu * mu + CEPS);
    const float4* gp = (const float4*)g;
    const float4* bp = (const float4*)b;
    float4 g0 = gp[lane], g1 = gp[lane + 32];
    float4 b0 = bp[lane], b1 = bp[lane + 32];
    float4 o0, o1;
    o0.x = (v0.x - mu) * rs * g0.x + b0.x;
    o0.y = (v0.y - mu) * rs * g0.y + b0.y;
    o0.z = (v0.z - mu) * rs * g0.z + b0.z;
    o0.w = (v0.w - mu) * rs * g0.w + b0.w;
    o1.x = (v1.x - mu) * rs * g1.x + b1.x;
    o1.y = (v1.y - mu) * rs * g1.y + b1.y;
    o1.z = (v1.z - mu) * rs * g1.z + b1.z;
    o1.w = (v1.w - mu) * rs * g1.w + b1.w;
    float4* op = (float4*)(out + (size_t)w * 256);
    op[lane] = o0;
    op[lane + 32] = o1;
}

// ---------------- bilinear sampling + softmax(4) + aggregation -------------------
__device__ __forceinline__ float fetch_v(const float* __restrict__ vb, int xi, int yi,
                                         int lane) {
    if ((unsigned)xi < 32u && (unsigned)yi < 32u)
        return vb[(((yi << 5) + xi) << 5) + lane];
    return 0.f;
}
__global__ __launch_bounds__(256) void sample_agg_kernel(const float* __restrict__ vflat,
                                                         const float* __restrict__ logits,
                                                         float* __restrict__ agg) {
    int wid = blockIdx.x * 8 + (threadIdx.x >> 5);
    int lane = threadIdx.x & 31;
    int q = wid & 4095, h = (wid >> 12) & 7, b = wid >> 15;

    const float* lp = logits + ((size_t)(b * 4096 + q)) * 32 + h * 4;
    float l0 = lp[0], l1 = lp[1], l2 = lp[2], l3 = lp[3];
    float m = fmaxf(fmaxf(l0, l1), fmaxf(l2, l3));
    float e0 = expf(l0 - m), e1 = expf(l1 - m), e2 = expf(l2 - m), e3 = expf(l3 - m);
    float inv = 1.f / (e0 + e1 + e2 + e3);
    float wp_[4] = {e0 * inv, e1 * inv, e2 * inv, e3 * inv};

    int qx = q & 63, qy = q >> 6;
    float bx = (qx + 0.5f) * 0.5f, by = (qy + 0.5f) * 0.5f;
    const float* vb = vflat + ((size_t)(b * 8 + h) << 10) * 32;

    float acc = 0.f;
#pragma unroll
    for (int p = 0; p < 4; p++) {
        float x = bx + g_offs[(h * 4 + p) * 2 + 0] - 0.5f;
        float y = by + g_offs[(h * 4 + p) * 2 + 1] - 0.5f;
        float xf = floorf(x), yf = floorf(y);
        int x0 = (int)xf, y0 = (int)yf;
        float fx = x - xf, fy = y - yf;
        float v00 = fetch_v(vb, x0, y0, lane);
        float v10 = fetch_v(vb, x0 + 1, y0, lane);
        float v01 = fetch_v(vb, x0, y0 + 1, lane);
        float v11 = fetch_v(vb, x0 + 1, y0 + 1, lane);
        float gg = (1.f - fx) * (1.f - fy) * v00 + fx * (1.f - fy) * v10 +
                   (1.f - fx) * fy * v01 + fx * fy * v11;
        acc = fmaf(wp_[p], gg, acc);
    }
    agg[((size_t)(b * 4096 + q)) * 256 + h * 32 + lane] = acc;
}

// ---------------- launch ----------------------------------------------------------
extern "C" void kernel_launch(void* const* d_in, const int* in_sizes, int n_in,
                              void* d_out, int out_size) {
    const float* query_feat = (const float*)d_in[0];
    const float* key_feat = (const float*)d_in[1];
    const float* qc_w = (const float*)d_in[2];
    const float* kc_w = (const float*)d_in[8];
    const float* off_res = (const float*)d_in[14];
    const float* lnq_g = (const float*)d_in[15];
    const float* lnq_b = (const float*)d_in[16];
    const float* lnk_g = (const float*)d_in[17];
    const float* lnk_b = (const float*)d_in[18];
    const float* lno_g = (const float*)d_in[19];
    const float* lno_b = (const float*)d_in[20];
    const float* vproj_w = (const float*)d_in[21];
    const float* vproj_b = (const float*)d_in[22];
    const float* aw_w = (const float*)d_in[23];
    const float* aw_b = (const float*)d_in[24];
    const float* oproj_w = (const float*)d_in[25];
    const float* oproj_b = (const float*)d_in[26];

    float *p_qf, *p_kf, *p_query, *p_kv, *p_value, *p_awlog, *p_agg;
    float *p_scale, *p_shift, *p_wB, *p_wT;
    cudaGetSymbolAddress((void**)&p_qf, g_qf);
    cudaGetSymbolAddress((void**)&p_kf, g_kf);
    cudaGetSymbolAddress((void**)&p_query, g_query);
    cudaGetSymbolAddress((void**)&p_kv, g_kv);
    cudaGetSymbolAddress((void**)&p_value, g_value);
    cudaGetSymbolAddress((void**)&p_awlog, g_awlog);
    cudaGetSymbolAddress((void**)&p_agg, g_agg);
    cudaGetSymbolAddress((void**)&p_scale, g_scale);
    cudaGetSymbolAddress((void**)&p_shift, g_shift);
    cudaGetSymbolAddress((void**)&p_wB, g_wB);
    cudaGetSymbolAddress((void**)&p_wT, g_wT);

    static cudaStream_t s2 = nullptr;
    static cudaEvent_t evFork = nullptr, evJoin = nullptr;
    if (s2 == nullptr) {
        cudaStreamCreateWithFlags(&s2, cudaStreamNonBlocking);
        cudaEventCreateWithFlags(&evFork, cudaEventDisableTiming);
        cudaEventCreateWithFlags(&evJoin, cudaEventDisableTiming);
    }

    const int SMC = 2 * 17408 + 2 * 40960;                       // 116736
    const int SMB = 4 * (32 * (256 * 2 + 16)) + 4 * (32 * 80);   // 77824
    cudaFuncSetAttribute(tconv<6>, cudaFuncAttributeMaxDynamicSharedMemorySize, SMC);
    cudaFuncSetAttribute(tconv<5>, cudaFuncAttributeMaxDynamicSharedMemorySize, SMC);
    cudaFuncSetAttribute(tproj<1>, cudaFuncAttributeMaxDynamicSharedMemorySize, SMC);
    cudaFuncSetAttribute(tprojF, cudaFuncAttributeMaxDynamicSharedMemorySize, SMC);
    cudaFuncSetAttribute(tgemm<256, 32, 8, 1>,
                         cudaFuncAttributeMaxDynamicSharedMemorySize, SMB);

    // ---- stream 0: prep, then fork ----
    prep_kernel<<<1, 256>>>((const float*)d_in[3], (const float*)d_in[4],
                            (const float*)d_in[5], (const float*)d_in[6],
                            (const float*)d_in[7], (const float*)d_in[9],
                            (const float*)d_in[10], (const float*)d_in[11],
                            (const float*)d_in[12], (const float*)d_in[13], off_res);
    cudaEventRecord(evFork, 0);

    // ---- side stream: K branch (hidden under tconv<6>) ----
    cudaStreamWaitEvent(s2, evFork, 0);
    convw_kernel<<<2304, 256, 0, s2>>>(kc_w, p_wB + 589824);
    tconv<5><<<64, 512, SMC, s2>>>(key_feat, p_wB + 589824, p_scale + 256,
                                   p_shift + 256, p_kf);
    ln_kernel<<<1024, 256, 0, s2>>>(p_kf, lnk_g, lnk_b, p_kv, 8192);
    wtprep_kernel<<<256, 256, 0, s2>>>(vproj_w, p_wT);
    wtprep_kernel<<<256, 256, 0, s2>>>(oproj_w, p_wT + 65536);
    tproj<1><<<64, 512, SMC, s2>>>(p_kv, p_wT, vproj_b, p_value);
    cudaEventRecord(evJoin, s2);

    // ---- stream 0: Q branch ----
    convw_kernel<<<2304, 256>>>(qc_w, p_wB);
    transpose_kernel<<<32, 256>>>(aw_w, p_wT + 131072, 256, 32);
    tconv<6><<<256, 512, SMC>>>(query_feat, p_wB, p_scale, p_shift, p_qf);
    ln_kernel<<<4096, 256>>>(p_qf, lnq_g, lnq_b, p_query, 32768);
    tgemm<256, 32, 8, 1><<<128, 256, SMB>>>(p_query, p_wT + 131072, aw_b, p_awlog, 256);

    // ---- join: sample needs vproj output ----
    cudaStreamWaitEvent(0, evJoin, 0);
    sample_agg_kernel<<<32768, 256>>>(p_value, p_awlog, p_agg);
    tprojF<<<256, 512, SMC>>>(p_agg, p_wT + 65536, oproj_b, p_query, lno_g, lno_b,
                              (float*)d_out);
}

// round 17
// speedup vs baseline: 1.0735x; 1.0002x over previous
#include <cuda_runtime.h>
#include <cuda_bf16.h>
#include <math.h>
#include <stdint.h>

#define CEPS 1e-5f

// ---------------- scratch (device globals; allocations forbidden) ----------------
__device__ float g_query[8 * 4096 * 256];
__device__ float g_kv[8 * 1024 * 256];
__device__ float g_value[8 * 8 * 1024 * 32];
__device__ float g_awlog[8 * 4096 * 32];
__device__ float g_agg[8 * 4096 * 256];
__device__ float g_scale[2][256];
__device__ float g_shift[2][256];
__device__ float g_offs[64];
__device__ float g_wB[2 * 589824];           // conv weights tf32, [oc][tap*256+ic], k-pair-interleaved
__device__ float g_wT[2 * 65536 + 8192];     // vprojT(itl tf32) | oprojT(itl tf32) | awT(fp32)

// ---------------- PTX helpers ----------------------------------------------------
__device__ __forceinline__ void mma16816(float* d, const uint32_t* a, uint32_t b0,
                                         uint32_t b1) {
    asm volatile(
        "mma.sync.aligned.m16n8k16.row.col.f32.bf16.bf16.f32 "
        "{%0,%1,%2,%3}, {%4,%5,%6,%7}, {%8,%9}, {%0,%1,%2,%3};\n"
        : "+f"(d[0]), "+f"(d[1]), "+f"(d[2]), "+f"(d[3])
        : "r"(a[0]), "r"(a[1]), "r"(a[2]), "r"(a[3]), "r"(b0), "r"(b1));
}
__device__ __forceinline__ void mma1688t(float* d, const uint32_t* a, uint32_t b0,
                                         uint32_t b1) {
    asm volatile(
        "mma.sync.aligned.m16n8k8.row.col.f32.tf32.tf32.f32 "
        "{%0,%1,%2,%3}, {%4,%5,%6,%7}, {%8,%9}, {%0,%1,%2,%3};\n"
        : "+f"(d[0]), "+f"(d[1]), "+f"(d[2]), "+f"(d[3])
        : "r"(a[0]), "r"(a[1]), "r"(a[2]), "r"(a[3]), "r"(b0), "r"(b1));
}
__device__ __forceinline__ void ldmx4(uint32_t* r, uint32_t addr) {
    asm volatile("ldmatrix.sync.aligned.m8n8.x4.shared.b16 {%0,%1,%2,%3}, [%4];"
                 : "=r"(r[0]), "=r"(r[1]), "=r"(r[2]), "=r"(r[3]) : "r"(addr));
}
__device__ __forceinline__ void ldmx4t(uint32_t* r, uint32_t addr) {
    asm volatile("ldmatrix.sync.aligned.m8n8.x4.trans.shared.b16 {%0,%1,%2,%3}, [%4];"
                 : "=r"(r[0]), "=r"(r[1]), "=r"(r[2]), "=r"(r[3]) : "r"(addr));
}
__device__ __forceinline__ uint32_t smem_u32(const void* p) {
    uint32_t a;
    asm("{ .reg .u64 t; cvta.to.shared.u64 t, %1; cvt.u32.u64 %0, t; }" : "=r"(a) : "l"(p));
    return a;
}
__device__ __forceinline__ void split2(float x, float y, uint32_t& hi, uint32_t& lo) {
    __nv_bfloat162 h = __floats2bfloat162_rn(x, y);
    float2 f = __bfloat1622float2(h);
    __nv_bfloat162 l = __floats2bfloat162_rn(x - f.x, y - f.y);
    hi = *reinterpret_cast<uint32_t*>(&h);
    lo = *reinterpret_cast<uint32_t*>(&l);
}
__device__ __forceinline__ uint32_t to_tf32(float x) {
    uint32_t r;
    asm("cvt.rna.tf32.f32 %0, %1;" : "=r"(r) : "f"(x));
    return r;
}
__device__ __forceinline__ void cpasync16(uint32_t dst, const void* src) {
    asm volatile("cp.async.ca.shared.global [%0], [%1], 16;" :: "r"(dst), "l"(src));
}
#define CP_COMMIT() asm volatile("cp.async.commit_group;" ::: "memory")
#define CP_WAIT0() asm volatile("cp.async.wait_group 0;" ::: "memory")

// ---------------- prep ------------------------------------------------------------
__global__ void prep_kernel(const float* __restrict__ qcb, const float* __restrict__ qg,
                            const float* __restrict__ qbb, const float* __restrict__ qm,
                            const float* __restrict__ qv,
                            const float* __restrict__ kcb, const float* __restrict__ kg,
                            const float* __restrict__ kbb, const float* __restrict__ km,
                            const float* __restrict__ kvv,
                            const float* __restrict__ off_res) {
    int t = threadIdx.x;
    if (t < 256) {
        float a = qg[t] * rsqrtf(qv[t] + CEPS);
        g_scale[0][t] = a;
        g_shift[0][t] = (qcb[t] - qm[t]) * a + qbb[t];
        float ak = kg[t] * rsqrtf(kvv[t] + CEPS);
        g_scale[1][t] = ak;
        g_shift[1][t] = (kcb[t] - km[t]) * ak + kbb[t];
    }
    if (t < 64) {
        int h = t >> 3, p = (t >> 1) & 3, d = t & 1;
        double PI2 = 6.283185307179586476925287;
        double th = PI2 * (double)p / 4.0 + PI2 * (double)h / 8.0;
        double r = 1.0 + (double)p;
        g_offs[t] = (float)(d == 0 ? r * cos(th) : r * sin(th)) + off_res[t];
    }
}

// conv weight reorder + tf32 + k-pair interleave within each 8-k group
__global__ void convw_kernel(const float* __restrict__ w, float* __restrict__ out) {
    int i = blockIdx.x * 256 + threadIdx.x;
    if (i < 256 * 2304) {
        int oc = i / 2304, kk = i - oc * 2304;
        int jp = kk & 7;
        int j = ((jp & 1) << 2) | (jp >> 1);
        int k = (kk & ~7) | j;
        int tap = k >> 8, ic = k & 255;
        uint32_t v = to_tf32(w[(oc * 256 + ic) * 9 + tap]);
        out[i] = __uint_as_float(v);
    }
}

// projection weight: w[k][n] ([256][256] row-major) -> out[n][kk] tf32, k-pair-itl
__global__ void wtprep_kernel(const float* __restrict__ w, float* __restrict__ out) {
    int i = blockIdx.x * 256 + threadIdx.x;
    if (i < 65536) {
        int n = i >> 8, kk = i & 255;
        int jp = kk & 7;
        int j = ((jp & 1) << 2) | (jp >> 1);
        int k = (kk & ~7) | j;
        uint32_t v = to_tf32(w[k * 256 + n]);
        out[i] = __uint_as_float(v);
    }
}

__global__ void transpose_kernel(const float* __restrict__ s, float* __restrict__ d,
                                 int R, int C) {
    int i = blockIdx.x * 256 + threadIdx.x;
    if (i < R * C) {
        int r = i / C, c = i - r * C;
        d[(size_t)c * R + r] = s[i];
    }
}

// ---- tf32 implicit-GEMM conv3x3 + BN + ReLU + fused LayerNorm -------------------
template <int LOGW>
__global__ __launch_bounds__(512, 1) void tconv(const float* __restrict__ A,
                                                const float* __restrict__ Bw,
                                                const float* __restrict__ e0,
                                                const float* __restrict__ e1,
                                                const float* __restrict__ lng,
                                                const float* __restrict__ lnb,
                                                float* __restrict__ out) {
    constexpr int W_ = 1 << LOGW, H_ = W_;
    constexpr int PA = 544;
    constexpr int SZA = 32 * PA;            // 17408
    constexpr int PB = 160;
    constexpr int SZB = 256 * PB;           // 40960
    constexpr int OFB = 2 * SZA;
    extern __shared__ char smem[];
    const int t = threadIdx.x, wid = t >> 5, lane = t & 31;
    const int m0 = blockIdx.x * 128;
    const int wm = (wid >> 2) * 32, wn = (wid & 3) * 64;
    const int grp = lane >> 2, tid4 = lane & 3;
    const uint32_t sb = smem_u32(smem);

    float acc[2][8][4];
#pragma unroll
    for (int a = 0; a < 2; a++)
#pragma unroll
        for (int b = 0; b < 8; b++)
#pragma unroll
            for (int c = 0; c < 4; c++) acc[a][b][c] = 0.f;

    const int kl = t >> 4, g = t & 15, moff = g * 8;
    const int p0 = m0 + moff;
    const int bb = p0 >> (2 * LOGW);
    const int pix = p0 & (H_ * W_ - 1);
    const int y = pix >> LOGW, x0 = pix & (W_ - 1);
    const bool vlo = (x0 > 0), vhi = (x0 + 8 < W_);

    float wv[16];

    auto ldg = [&](int ck, int nb) {
        const int k0 = ck << 5;
        const int tap = k0 >> 8;
        const int ky = tap / 3 - 1;
        const int ic = (k0 & 255) + kl;
        const int yy = y + ky;
        const bool vy = (unsigned)yy < (unsigned)H_;
        const float* src = A + (((size_t)(bb * 256 + ic) * H_ + yy) << LOGW) + x0 - 4;
#pragma unroll
        for (int j = 0; j < 4; j++) {
            float4 v = make_float4(0.f, 0.f, 0.f, 0.f);
            bool ok = vy && (j > 0 || vlo) && (j < 3 || vhi);
            if (ok) v = __ldg((const float4*)(src + 4 * j));
            wv[4 * j] = v.x; wv[4 * j + 1] = v.y; wv[4 * j + 2] = v.z; wv[4 * j + 3] = v.w;
        }
        const int n = t >> 1, hf = t & 1;
        const float* bs = Bw + (size_t)n * 2304 + k0 + hf * 16;
        uint32_t bd = sb + OFB + nb * SZB + n * PB + hf * 64;
#pragma unroll
        for (int j = 0; j < 4; j++) cpasync16(bd + j * 16, bs + j * 4);
        CP_COMMIT();
    };

    auto stage_a = [&](int nb, int kx) {
        char* aB = smem + nb * SZA;
        uint32_t u[8];
        if (kx == -1) {
#pragma unroll
            for (int j = 0; j < 8; j++) u[j] = to_tf32(wv[3 + j]);
        } else if (kx == 0) {
#pragma unroll
            for (int j = 0; j < 8; j++) u[j] = to_tf32(wv[4 + j]);
        } else {
#pragma unroll
            for (int j = 0; j < 8; j++) u[j] = to_tf32(wv[5 + j]);
        }
        uint4* d = (uint4*)(aB + kl * PA + moff * 4);
        d[0] = make_uint4(u[0], u[1], u[2], u[3]);
        d[1] = make_uint4(u[4], u[5], u[6], u[7]);
    };

    auto compute = [&](int buf) {
        const char* aB = smem + buf * SZA;
        const char* bB = smem + OFB + buf * SZB;
#pragma unroll
        for (int ks = 0; ks < 4; ks++) {
            const int ko = ks * 8;
            uint32_t af[2][4];
#pragma unroll
            for (int mi = 0; mi < 2; mi++) {
                int r = wm + mi * 16 + grp;
                const char* a0 = aB + (ko + tid4) * PA + r * 4;
                af[mi][0] = *(const uint32_t*)(a0);
                af[mi][1] = *(const uint32_t*)(a0 + 32);
                af[mi][2] = *(const uint32_t*)(a0 + 4 * PA);
                af[mi][3] = *(const uint32_t*)(a0 + 4 * PA + 32);
            }
#pragma unroll
            for (int np = 0; np < 8; np++) {
                int n = wn + np * 8 + grp;
                uint2 bv = *(const uint2*)(bB + n * PB + ko * 4 + tid4 * 8);
                mma1688t(acc[0][np], af[0], bv.x, bv.y);
                mma1688t(acc[1][np], af[1], bv.x, bv.y);
            }
        }
    };

    const int nk = 72;
    ldg(0, 0);
    stage_a(0, -1);
    CP_WAIT0();
    __syncthreads();

    for (int i = 0; i < nk; i++) {
        const int buf = i & 1, nb = buf ^ 1;
        int kxn = 0;
        if (i + 1 < nk) {
            ldg(i + 1, nb);
            kxn = ((i + 1) >> 3) % 3 - 1;
        }
        compute(buf);
        if (i + 1 < nk) {
            stage_a(nb, kxn);
            CP_WAIT0();
        }
        __syncthreads();
    }

    // ---- fused epilogue: relu(acc*scale+shift) -> LayerNorm(C=256) -> row-major --
    float* redS = (float*)smem;  // [128 rows][4 wn-warps][2]
    float s_[2][2], ss_[2][2];
#pragma unroll
    for (int mi = 0; mi < 2; mi++)
#pragma unroll
        for (int rl = 0; rl < 2; rl++) { s_[mi][rl] = 0.f; ss_[mi][rl] = 0.f; }

#pragma unroll
    for (int mi = 0; mi < 2; mi++) {
#pragma unroll
        for (int np = 0; np < 8; np++) {
            int c = wn + np * 8 + tid4 * 2;
            float s0 = e0[c], s1 = e0[c + 1], h0 = e1[c], h1 = e1[c + 1];
            float o00 = fmaxf(acc[mi][np][0] * s0 + h0, 0.f);
            float o01 = fmaxf(acc[mi][np][1] * s1 + h1, 0.f);
            float o10 = fmaxf(acc[mi][np][2] * s0 + h0, 0.f);
            float o11 = fmaxf(acc[mi][np][3] * s1 + h1, 0.f);
            acc[mi][np][0] = o00; acc[mi][np][1] = o01;
            acc[mi][np][2] = o10; acc[mi][np][3] = o11;
            s_[mi][0] += o00 + o01; ss_[mi][0] += o00 * o00 + o01 * o01;
            s_[mi][1] += o10 + o11; ss_[mi][1] += o10 * o10 + o11 * o11;
        }
    }
#pragma unroll
    for (int mi = 0; mi < 2; mi++)
#pragma unroll
        for (int rl = 0; rl < 2; rl++) {
            float s = s_[mi][rl], ss = ss_[mi][rl];
            s += __shfl_xor_sync(0xffffffffu, s, 1);
            ss += __shfl_xor_sync(0xffffffffu, ss, 1);
            s += __shfl_xor_sync(0xffffffffu, s, 2);
            ss += __shfl_xor_sync(0xffffffffu, ss, 2);
            s_[mi][rl] = s; ss_[mi][rl] = ss;
        }
    __syncthreads();
    if (tid4 == 0) {
#pragma unroll
        for (int mi = 0; mi < 2; mi++)
#pragma unroll
            for (int rl = 0; rl < 2; rl++) {
                int rloc = wm + mi * 16 + rl * 8 + grp;
                redS[rloc * 8 + (wid & 3) * 2 + 0] = s_[mi][rl];
                redS[rloc * 8 + (wid & 3) * 2 + 1] = ss_[mi][rl];
            }
    }
    __syncthreads();

#pragma unroll
    for (int mi = 0; mi < 2; mi++) {
#pragma unroll
        for (int rl = 0; rl < 2; rl++) {
            int rloc = wm + mi * 16 + rl * 8 + grp;
            float s = redS[rloc * 8 + 0] + redS[rloc * 8 + 2] + redS[rloc * 8 + 4] +
                      redS[rloc * 8 + 6];
            float ss = redS[rloc * 8 + 1] + redS[rloc * 8 + 3] + redS[rloc * 8 + 5] +
                       redS[rloc * 8 + 7];
            float mu = s * (1.f / 256.f);
            float rs = rsqrtf(ss * (1.f / 256.f) - mu * mu + CEPS);
            int row = m0 + rloc;
#pragma unroll
            for (int np = 0; np < 8; np++) {
                int c = wn + np * 8 + tid4 * 2;
                float o0 = acc[mi][np][2 * rl + 0];
                float o1 = acc[mi][np][2 * rl + 1];
                float r0 = (o0 - mu) * rs * __ldg(&lng[c]) + __ldg(&lnb[c]);
                float r1 = (o1 - mu) * rs * __ldg(&lng[c + 1]) + __ldg(&lnb[c + 1]);
                *(float2*)&out[(size_t)row * 256 + c] = make_float2(r0, r1);
            }
        }
    }
}

// ---------------- tf32 projection GEMM: out = A[M,256] x W^T ---------------------
template <int MODE>
__global__ __launch_bounds__(512, 1) void tproj(const float* __restrict__ A,
                                                const float* __restrict__ Bw,
                                                const float* __restrict__ bias,
                                                float* __restrict__ out) {
    constexpr int PA = 544;
    constexpr int SZA = 32 * PA;
    constexpr int PB = 160;
    constexpr int SZB = 256 * PB;
    constexpr int OFB = 2 * SZA;
    extern __shared__ char smem[];
    const int t = threadIdx.x, wid = t >> 5, lane = t & 31;
    const int m0 = blockIdx.x * 128;
    const int wm = (wid >> 2) * 32, wn = (wid & 3) * 64;
    const int grp = lane >> 2, tid4 = lane & 3;
    const uint32_t sb = smem_u32(smem);

    float acc[2][8][4];
#pragma unroll
    for (int a = 0; a < 2; a++)
#pragma unroll
        for (int b = 0; b < 8; b++)
#pragma unroll
            for (int c = 0; c < 4; c++) acc[a][b][c] = 0.f;

    const int mrow = t & 127, kh = (t >> 7) * 8;

    auto ldgB = [&](int ck, int nb) {
        const int k0 = ck << 5;
        const int n = t >> 1, hf = t & 1;
        const float* bs = Bw + (size_t)n * 256 + k0 + hf * 16;
        uint32_t bd = sb + OFB + nb * SZB + n * PB + hf * 64;
#pragma unroll
        for (int j = 0; j < 4; j++) cpasync16(bd + j * 16, bs + j * 4);
        CP_COMMIT();
    };

    auto stage_a = [&](int ck, int nb) {
        const int k0 = ck << 5;
        const float* src = A + (size_t)(m0 + mrow) * 256 + k0 + kh;
        float4 v0 = __ldg((const float4*)src);
        float4 v1 = __ldg((const float4*)(src + 4));
        float w8[8] = {v0.x, v0.y, v0.z, v0.w, v1.x, v1.y, v1.z, v1.w};
        char* aB = smem + nb * SZA;
#pragma unroll
        for (int j = 0; j < 8; j++)
            *(uint32_t*)(aB + (kh + j) * PA + mrow * 4) = to_tf32(w8[j]);
    };

    auto compute = [&](int buf) {
        const char* aB = smem + buf * SZA;
        const char* bB = smem + OFB + buf * SZB;
#pragma unroll
        for (int ks = 0; ks < 4; ks++) {
            const int ko = ks * 8;
            uint32_t af[2][4];
#pragma unroll
            for (int mi = 0; mi < 2; mi++) {
                int r = wm + mi * 16 + grp;
                const char* a0 = aB + (ko + tid4) * PA + r * 4;
                af[mi][0] = *(const uint32_t*)(a0);
                af[mi][1] = *(const uint32_t*)(a0 + 32);
                af[mi][2] = *(const uint32_t*)(a0 + 4 * PA);
                af[mi][3] = *(const uint32_t*)(a0 + 4 * PA + 32);
            }
#pragma unroll
            for (int np = 0; np < 8; np++) {
                int n = wn + np * 8 + grp;
                uint2 bv = *(const uint2*)(bB + n * PB + ko * 4 + tid4 * 8);
                mma1688t(acc[0][np], af[0], bv.x, bv.y);
                mma1688t(acc[1][np], af[1], bv.x, bv.y);
            }
        }
    };

    const int nk = 8;
    ldgB(0, 0);
    stage_a(0, 0);
    CP_WAIT0();
    __syncthreads();

    for (int i = 0; i < nk; i++) {
        const int buf = i & 1, nb = buf ^ 1;
        if (i + 1 < nk) ldgB(i + 1, nb);
        compute(buf);
        if (i + 1 < nk) {
            stage_a(i + 1, nb);
            CP_WAIT0();
        }
        __syncthreads();
    }

#pragma unroll
    for (int mi = 0; mi < 2; mi++)
#pragma unroll
        for (int np = 0; np < 8; np++) {
            int r0 = m0 + wm + mi * 16 + grp;
            int c = wn + np * 8 + tid4 * 2;
            float b0 = bias[c], b1 = bias[c + 1];
            float v00 = acc[mi][np][0] + b0, v01 = acc[mi][np][1] + b1;
            float v10 = acc[mi][np][2] + b0, v11 = acc[mi][np][3] + b1;
            if (MODE == 1) {
                int h = c >> 5, d = c & 31;
                int r1 = r0 + 8;
                *(float2*)&out[((size_t)(((r0 >> 10) * 8 + h) * 1024 + (r0 & 1023))) * 32 + d] =
                    make_float2(v00, v01);
                *(float2*)&out[((size_t)(((r1 >> 10) * 8 + h) * 1024 + (r1 & 1023))) * 32 + d] =
                    make_float2(v10, v11);
            } else {
                *(float2*)&out[(size_t)r0 * 256 + c] = make_float2(v00, v01);
                *(float2*)&out[(size_t)(r0 + 8) * 256 + c] = make_float2(v10, v11);
            }
        }
}

// ---------------- fused oproj + q*(1+attn) + LayerNorm + NCHW store --------------
__global__ __launch_bounds__(512, 1) void tprojF(const float* __restrict__ A,
                                                 const float* __restrict__ Bw,
                                                 const float* __restrict__ bias,
                                                 const float* __restrict__ query,
                                                 const float* __restrict__ lng,
                                                 const float* __restrict__ lnb,
                                                 float* __restrict__ out) {
    constexpr int PA = 544;
    constexpr int SZA = 32 * PA;
    constexpr int PB = 160;
    constexpr int SZB = 256 * PB;
    constexpr int OFB = 2 * SZA;
    extern __shared__ char smem[];
    const int t = threadIdx.x, wid = t >> 5, lane = t & 31;
    const int m0 = blockIdx.x * 128;
    const int wm = (wid >> 2) * 32, wn = (wid & 3) * 64;
    const int grp = lane >> 2, tid4 = lane & 3;
    const uint32_t sb = smem_u32(smem);

    float acc[2][8][4];
#pragma unroll
    for (int a = 0; a < 2; a++)
#pragma unroll
        for (int b = 0; b < 8; b++)
#pragma unroll
            for (int c = 0; c < 4; c++) acc[a][b][c] = 0.f;

    const int mrow = t & 127, kh = (t >> 7) * 8;

    auto ldgB = [&](int ck, int nb) {
        const int k0 = ck << 5;
        const int n = t >> 1, hf = t & 1;
        const float* bs = Bw + (size_t)n * 256 + k0 + hf * 16;
        uint32_t bd = sb + OFB + nb * SZB + n * PB + hf * 64;
#pragma unroll
        for (int j = 0; j < 4; j++) cpasync16(bd + j * 16, bs + j * 4);
        CP_COMMIT();
    };

    auto stage_a = [&](int ck, int nb) {
        const int k0 = ck << 5;
        const float* src = A + (size_t)(m0 + mrow) * 256 + k0 + kh;
        float4 v0 = __ldg((const float4*)src);
        float4 v1 = __ldg((const float4*)(src + 4));
        float w8[8] = {v0.x, v0.y, v0.z, v0.w, v1.x, v1.y, v1.z, v1.w};
        char* aB = smem + nb * SZA;
#pragma unroll
        for (int j = 0; j < 8; j++)
            *(uint32_t*)(aB + (kh + j) * PA + mrow * 4) = to_tf32(w8[j]);
    };

    auto compute = [&](int buf) {
        const char* aB = smem + buf * SZA;
        const char* bB = smem + OFB + buf * SZB;
#pragma unroll
        for (int ks = 0; ks < 4; ks++) {
            const int ko = ks * 8;
            uint32_t af[2][4];
#pragma unroll
            for (int mi = 0; mi < 2; mi++) {
                int r = wm + mi * 16 + grp;
                const char* a0 = aB + (ko + tid4) * PA + r * 4;
                af[mi][0] = *(const uint32_t*)(a0);
                af[mi][1] = *(const uint32_t*)(a0 + 32);
                af[mi][2] = *(const uint32_t*)(a0 + 4 * PA);
                af[mi][3] = *(const uint32_t*)(a0 + 4 * PA + 32);
            }
#pragma unroll
            for (int np = 0; np < 8; np++) {
                int n = wn + np * 8 + grp;
                uint2 bv = *(const uint2*)(bB + n * PB + ko * 4 + tid4 * 8);
                mma1688t(acc[0][np], af[0], bv.x, bv.y);
                mma1688t(acc[1][np], af[1], bv.x, bv.y);
            }
        }
    };

    const int nk = 8;
    ldgB(0, 0);
    stage_a(0, 0);
    CP_WAIT0();
    __syncthreads();

    for (int i = 0; i < nk; i++) {
        const int buf = i & 1, nb = buf ^ 1;
        if (i + 1 < nk) ldgB(i + 1, nb);
        compute(buf);
        if (i + 1 < nk) {
            stage_a(i + 1, nb);
            CP_WAIT0();
        }
        __syncthreads();
    }

    // ---- fused epilogue: o = q*(1+acc+bias); LN over C=256; NCHW store ----
    float* redS = (float*)smem;
    float s_[2][2], ss_[2][2];
#pragma unroll
    for (int mi = 0; mi < 2; mi++)
#pragma unroll
        for (int rl = 0; rl < 2; rl++) { s_[mi][rl] = 0.f; ss_[mi][rl] = 0.f; }

#pragma unroll
    for (int mi = 0; mi < 2; mi++) {
        int r0 = m0 + wm + mi * 16 + grp;
#pragma unroll
        for (int np = 0; np < 8; np++) {
            int c = wn + np * 8 + tid4 * 2;
            float b0 = bias[c], b1 = bias[c + 1];
            float2 qa = *(const float2*)&query[(size_t)r0 * 256 + c];
            float2 qb = *(const float2*)&query[(size_t)(r0 + 8) * 256 + c];
            float o00 = qa.x * (1.f + acc[mi][np][0] + b0);
            float o01 = qa.y * (1.f + acc[mi][np][1] + b1);
            float o10 = qb.x * (1.f + acc[mi][np][2] + b0);
            float o11 = qb.y * (1.f + acc[mi][np][3] + b1);
            acc[mi][np][0] = o00; acc[mi][np][1] = o01;
            acc[mi][np][2] = o10; acc[mi][np][3] = o11;
            s_[mi][0] += o00 + o01; ss_[mi][0] += o00 * o00 + o01 * o01;
            s_[mi][1] += o10 + o11; ss_[mi][1] += o10 * o10 + o11 * o11;
        }
    }
#pragma unroll
    for (int mi = 0; mi < 2; mi++)
#pragma unroll
        for (int rl = 0; rl < 2; rl++) {
            float s = s_[mi][rl], ss = ss_[mi][rl];
            s += __shfl_xor_sync(0xffffffffu, s, 1);
            ss += __shfl_xor_sync(0xffffffffu, ss, 1);
            s += __shfl_xor_sync(0xffffffffu, s, 2);
            ss += __shfl_xor_sync(0xffffffffu, ss, 2);
            s_[mi][rl] = s; ss_[mi][rl] = ss;
        }
    __syncthreads();
    if (tid4 == 0) {
#pragma unroll
        for (int mi = 0; mi < 2; mi++)
#pragma unroll
            for (int rl = 0; rl < 2; rl++) {
                int rloc = wm + mi * 16 + rl * 8 + grp;
                redS[rloc * 8 + (wid & 3) * 2 + 0] = s_[mi][rl];
                redS[rloc * 8 + (wid & 3) * 2 + 1] = ss_[mi][rl];
            }
    }
    __syncthreads();

    const int bB_ = m0 >> 12;
    const int pixBase = m0 & 4095;
#pragma unroll
    for (int mi = 0; mi < 2; mi++) {
#pragma unroll
        for (int rl = 0; rl < 2; rl++) {
            int rloc = wm + mi * 16 + rl * 8 + grp;
            float s = redS[rloc * 8 + 0] + redS[rloc * 8 + 2] + redS[rloc * 8 + 4] +
                      redS[rloc * 8 + 6];
            float ss = redS[rloc * 8 + 1] + redS[rloc * 8 + 3] + redS[rloc * 8 + 5] +
                       redS[rloc * 8 + 7];
            float mu = s * (1.f / 256.f);
            float rs = rsqrtf(ss * (1.f / 256.f) - mu * mu + CEPS);
            int pix = pixBase + rloc;
#pragma unroll
            for (int np = 0; np < 8; np++) {
                int c = wn + np * 8 + tid4 * 2;
                float o0 = acc[mi][np][2 * rl + 0];
                float o1 = acc[mi][np][2 * rl + 1];
                float r0 = (o0 - mu) * rs * __ldg(&lng[c]) + __ldg(&lnb[c]);
                float r1 = (o1 - mu) * rs * __ldg(&lng[c + 1]) + __ldg(&lnb[c + 1]);
                out[((size_t)(bB_ * 256 + c) << 12) + pix] = r0;
                out[((size_t)(bB_ * 256 + c + 1) << 12) + pix] = r1;
            }
        }
    }
}

// ---------------- bf16 HMMA GEMM (aw logits only) --------------------------------
template <int BM, int BN, int WGM, int WGN>
__global__ __launch_bounds__(256, 1) void tgemm(const float* __restrict__ A,
                                                const float* __restrict__ B,
                                                const float* __restrict__ e0,
                                                float* __restrict__ out, int K) {
    constexpr int WM = BM / WGM, WN = BN / WGN;
    constexpr int MI = WM / 16, NT = WN / 8, NT2 = WN / 16;
    constexpr int PA = BM * 2 + 16;
    constexpr int SZA = 32 * PA;
    constexpr int SZB = BN * 80;
    constexpr int EPTA = BM / 8;
    constexpr int EPTB = BN / 8;
    extern __shared__ char smem[];
    const uint32_t sb = smem_u32(smem);
    const int t = threadIdx.x, wid = t >> 5, lane = t & 31;
    const int m0 = blockIdx.x * BM;
    const int wm = (wid / WGN) * WM, wn = (wid % WGN) * WN;
    const int lq = lane & 7, lb3 = (lane >> 3) & 1, lb4 = (lane >> 4) & 1;

    float acc[MI][NT][4];
#pragma unroll
    for (int a = 0; a < MI; a++)
#pragma unroll
        for (int b = 0; b < NT; b++)
#pragma unroll
            for (int c = 0; c < 4; c++) acc[a][b][c] = 0.f;

    float va[EPTA], vb[EPTB];
    const int nk = K >> 5;

    auto ldg = [&](int ck) {
        const int k0 = ck << 5;
        const float4* s = (const float4*)(A + (size_t)(m0 + t) * K + k0);
#pragma unroll
        for (int j = 0; j < 8; j++) ((float4*)va)[j] = __ldg(s + j);
        const float4* s2 = (const float4*)(B + (size_t)(t >> 3) * K + k0 + (t & 7) * 4);
        ((float4*)vb)[0] = __ldg(s2);
    };

    auto sts = [&](int buf) {
        char* aHi = smem + buf * (2 * SZA);
        char* aLo = aHi + SZA;
        char* bHi = smem + 4 * SZA + buf * (2 * SZB);
        char* bLo = bHi + SZB;
#pragma unroll
        for (int j = 0; j < 32; j++) {
            __nv_bfloat16 hb = __float2bfloat16(va[j]);
            float r = va[j] - __bfloat162float(hb);
            *(__nv_bfloat16*)(aHi + j * PA + t * 2) = hb;
            *(__nv_bfloat16*)(aLo + j * PA + t * 2) = __float2bfloat16(r);
        }
        int n = t >> 3, kq = (t & 7) * 4;
        uint32_t* h = (uint32_t*)(bHi + n * 80 + kq * 2);
        uint32_t* l = (uint32_t*)(bLo + n * 80 + kq * 2);
#pragma unroll
        for (int j = 0; j < 2; j++) {
            uint32_t hh, ll;
            split2(vb[2 * j], vb[2 * j + 1], hh, ll);
            h[j] = hh;
            l[j] = ll;
        }
    };

    auto compute = [&](int buf) {
        uint32_t aHi = sb + buf * (2 * SZA), aLo = aHi + SZA;
        uint32_t bHi = sb + 4 * SZA + buf * (2 * SZB), bLo = bHi + SZB;
#pragma unroll
        for (int ks = 0; ks < 2; ks++) {
            uint32_t ah[MI][4], al[MI][4];
#pragma unroll
            for (int mi = 0; mi < MI; mi++) {
                uint32_t ao = (uint32_t)((ks * 16 + lq + lb4 * 8) * PA +
                                         (wm + mi * 16 + lb3 * 8) * 2);
                ldmx4t(ah[mi], aHi + ao);
                ldmx4t(al[mi], aLo + ao);
            }
#pragma unroll
            for (int np = 0; np < NT2; np++) {
                uint32_t bo = (uint32_t)((wn + np * 16 + lq + lb3 * 8) * 80 +
                                         (ks * 16 + lb4 * 8) * 2);
                uint32_t bh[4], bl[4];
                ldmx4(bh, bHi + bo);
                ldmx4(bl, bLo + bo);
#pragma unroll
                for (int mi = 0; mi < MI; mi++) {
                    mma16816(acc[mi][2 * np], ah[mi], bh[0], bh[2]);
                    mma16816(acc[mi][2 * np + 1], ah[mi], bh[1], bh[3]);
                    mma16816(acc[mi][2 * np], al[mi], bh[0], bh[2]);
                    mma16816(acc[mi][2 * np + 1], al[mi], bh[1], bh[3]);
                    mma16816(acc[mi][2 * np], ah[mi], bl[0], bl[2]);
                    mma16816(acc[mi][2 * np + 1], ah[mi], bl[1], bl[3]);
                }
            }
        }
    };

    ldg(0);
    sts(0);
    __syncthreads();
    for (int i = 0; i < nk; i++) {
        if (i + 1 < nk) ldg(i + 1);
        compute(i & 1);
        if (i + 1 < nk) sts((i + 1) & 1);
        __syncthreads();
    }

#pragma unroll
    for (int mi = 0; mi < MI; mi++)
#pragma unroll
        for (int nt = 0; nt < NT; nt++) {
            int r0 = m0 + wm + mi * 16 + (lane >> 2);
            int c = wn + nt * 8 + (lane & 3) * 2;
            float b0 = e0[c], b1 = e0[c + 1];
            *(float2*)&out[(size_t)r0 * BN + c] =
                make_float2(acc[mi][nt][0] + b0, acc[mi][nt][1] + b1);
            *(float2*)&out[(size_t)(r0 + 8) * BN + c] =
                make_float2(acc[mi][nt][2] + b0, acc[mi][nt][3] + b1);
        }
}

// ---------------- bilinear sampling + softmax(4) + aggregation -------------------
__device__ __forceinline__ float fetch_v(const float* __restrict__ vb, int xi, int yi,
                                         int lane) {
    if ((unsigned)xi < 32u && (unsigned)yi < 32u)
        return vb[(((yi << 5) + xi) << 5) + lane];
    return 0.f;
}
__global__ __launch_bounds__(256) void sample_agg_kernel(const float* __restrict__ vflat,
                                                         const float* __restrict__ logits,
                                                         float* __restrict__ agg) {
    int wid = blockIdx.x * 8 + (threadIdx.x >> 5);
    int lane = threadIdx.x & 31;
    int q = wid & 4095, h = (wid >> 12) & 7, b = wid >> 15;

    const float* lp = logits + ((size_t)(b * 4096 + q)) * 32 + h * 4;
    float l0 = lp[0], l1 = lp[1], l2 = lp[2], l3 = lp[3];
    float m = fmaxf(fmaxf(l0, l1), fmaxf(l2, l3));
    float e0 = expf(l0 - m), e1 = expf(l1 - m), e2 = expf(l2 - m), e3 = expf(l3 - m);
    float inv = 1.f / (e0 + e1 + e2 + e3);
    float wp_[4] = {e0 * inv, e1 * inv, e2 * inv, e3 * inv};

    int qx = q & 63, qy = q >> 6;
    float bx = (qx + 0.5f) * 0.5f, by = (qy + 0.5f) * 0.5f;
    const float* vb = vflat + ((size_t)(b * 8 + h) << 10) * 32;

    float acc = 0.f;
#pragma unroll
    for (int p = 0; p < 4; p++) {
        float x = bx + g_offs[(h * 4 + p) * 2 + 0] - 0.5f;
        float y = by + g_offs[(h * 4 + p) * 2 + 1] - 0.5f;
        float xf = floorf(x), yf = floorf(y);
        int x0 = (int)xf, y0 = (int)yf;
        float fx = x - xf, fy = y - yf;
        float v00 = fetch_v(vb, x0, y0, lane);
        float v10 = fetch_v(vb, x0 + 1, y0, lane);
        float v01 = fetch_v(vb, x0, y0 + 1, lane);
        float v11 = fetch_v(vb, x0 + 1, y0 + 1, lane);
        float gg = (1.f - fx) * (1.f - fy) * v00 + fx * (1.f - fy) * v10 +
                   (1.f - fx) * fy * v01 + fx * fy * v11;
        acc = fmaf(wp_[p], gg, acc);
    }
    agg[((size_t)(b * 4096 + q)) * 256 + h * 32 + lane] = acc;
}

// ---------------- launch ----------------------------------------------------------
extern "C" void kernel_launch(void* const* d_in, const int* in_sizes, int n_in,
                              void* d_out, int out_size) {
    const float* query_feat = (const float*)d_in[0];
    const float* key_feat = (const float*)d_in[1];
    const float* qc_w = (const float*)d_in[2];
    const float* kc_w = (const float*)d_in[8];
    const float* off_res = (const float*)d_in[14];
    const float* lnq_g = (const float*)d_in[15];
    const float* lnq_b = (const float*)d_in[16];
    const float* lnk_g = (const float*)d_in[17];
    const float* lnk_b = (const float*)d_in[18];
    const float* lno_g = (const float*)d_in[19];
    const float* lno_b = (const float*)d_in[20];
    const float* vproj_w = (const float*)d_in[21];
    const float* vproj_b = (const float*)d_in[22];
    const float* aw_w = (const float*)d_in[23];
    const float* aw_b = (const float*)d_in[24];
    const float* oproj_w = (const float*)d_in[25];
    const float* oproj_b = (const float*)d_in[26];

    float *p_query, *p_kv, *p_value, *p_awlog, *p_agg;
    float *p_scale, *p_shift, *p_wB, *p_wT;
    cudaGetSymbolAddress((void**)&p_query, g_query);
    cudaGetSymbolAddress((void**)&p_kv, g_kv);
    cudaGetSymbolAddress((void**)&p_value, g_value);
    cudaGetSymbolAddress((void**)&p_awlog, g_awlog);
    cudaGetSymbolAddress((void**)&p_agg, g_agg);
    cudaGetSymbolAddress((void**)&p_scale, g_scale);
    cudaGetSymbolAddress((void**)&p_shift, g_shift);
    cudaGetSymbolAddress((void**)&p_wB, g_wB);
    cudaGetSymbolAddress((void**)&p_wT, g_wT);

    static cudaStream_t s2 = nullptr;
    static cudaEvent_t evFork = nullptr, evJoin = nullptr;
    if (s2 == nullptr) {
        cudaStreamCreateWithFlags(&s2, cudaStreamNonBlocking);
        cudaEventCreateWithFlags(&evFork, cudaEventDisableTiming);
        cudaEventCreateWithFlags(&evJoin, cudaEventDisableTiming);
    }

    const int SMC = 2 * 17408 + 2 * 40960;                       // 116736
    const int SMB = 4 * (32 * (256 * 2 + 16)) + 4 * (32 * 80);   // 77824
    cudaFuncSetAttribute(tconv<6>, cudaFuncAttributeMaxDynamicSharedMemorySize, SMC);
    cudaFuncSetAttribute(tconv<5>, cudaFuncAttributeMaxDynamicSharedMemorySize, SMC);
    cudaFuncSetAttribute(tproj<1>, cudaFuncAttributeMaxDynamicSharedMemorySize, SMC);
    cudaFuncSetAttribute(tprojF, cudaFuncAttributeMaxDynamicSharedMemorySize, SMC);
    cudaFuncSetAttribute(tgemm<256, 32, 8, 1>,
                         cudaFuncAttributeMaxDynamicSharedMemorySize, SMB);

    // ---- stream 0: prep, then fork ----
    prep_kernel<<<1, 256>>>((const float*)d_in[3], (const float*)d_in[4],
                            (const float*)d_in[5], (const float*)d_in[6],
                            (const float*)d_in[7], (const float*)d_in[9],
                            (const float*)d_in[10], (const float*)d_in[11],
                            (const float*)d_in[12], (const float*)d_in[13], off_res);
    cudaEventRecord(evFork, 0);

    // ---- side stream: K branch (conv-k + LN fused, vproj) ----
    cudaStreamWaitEvent(s2, evFork, 0);
    convw_kernel<<<2304, 256, 0, s2>>>(kc_w, p_wB + 589824);
    tconv<5><<<64, 512, SMC, s2>>>(key_feat, p_wB + 589824, p_scale + 256,
                                   p_shift + 256, lnk_g, lnk_b, p_kv);
    wtprep_kernel<<<256, 256, 0, s2>>>(vproj_w, p_wT);
    wtprep_kernel<<<256, 256, 0, s2>>>(oproj_w, p_wT + 65536);
    tproj<1><<<64, 512, SMC, s2>>>(p_kv, p_wT, vproj_b, p_value);
    cudaEventRecord(evJoin, s2);

    // ---- stream 0: Q branch (conv-q + LN fused, aw) ----
    convw_kernel<<<2304, 256>>>(qc_w, p_wB);
    transpose_kernel<<<32, 256>>>(aw_w, p_wT + 131072, 256, 32);
    tconv<6><<<256, 512, SMC>>>(query_feat, p_wB, p_scale, p_shift, lnq_g, lnq_b,
                                p_query);
    tgemm<256, 32, 8, 1><<<128, 256, SMB>>>(p_query, p_wT + 131072, aw_b, p_awlog, 256);

    // ---- join: sample needs vproj output ----
    cudaStreamWaitEvent(0, evJoin, 0);
    sample_agg_kernel<<<32768, 256>>>(p_value, p_awlog, p_agg);
    tprojF<<<256, 512, SMC>>>(p_agg, p_wT + 65536, oproj_b, p_query, lno_g, lno_b,
                              (float*)d_out);
}